// round 13
// baseline (speedup 1.0000x reference)
#include <cuda_runtime.h>
#include <cuda_bf16.h>
#include <math.h>

#define B_ 32
#define T_ 64
#define N_ 128
#define D_ 64
#define K2 129              // 2D+1 (source layout)
#define KD (K2*D_)          // 8256 (source stride)
#define KR 132              // padded k rows: [x 0..63 | rs 64 | pad 65..67 | h 68..131]
#define KD132 (KR*D_)       // 8448
#define HSZ (B_*N_*D_)
#define NBT (B_*T_)         // 2048 (b,t) pairs
#define GRID 128
#define BLOCK 1024

// ---- smem layout (floats) ----
#define OFF_W     0                    // 3*KD132 = 25344 (W[g][k][d], k-major rows of 64)
#define OFF_BEFF  (3*KD132)            // 192
#define U_OFF     (3*KD132 + 192)      // union scratch
#define U_SIZE    17200
#define HS_OFF    (U_OFF + U_SIZE)     // persistent h [32][64] = 2048
#define SMEM_FLOATS (HS_OFF + 2048)
#define SMEM_BYTES  (SMEM_FLOATS*4 + 64)

// ---- device scratch ----
__device__ float g_invtot[B_*N_];
__device__ float g_rs[NBT*N_];                       // rs for all (b,t,n)
__device__ float g_hbuf[2*HSZ];
__device__ float g_combH[B_*N_*D_];                  // per-step A(t)@h
__device__ float g_combx[(size_t)NBT*N_*68];         // A(t)@[x|rs], pads 66..67 stay 0
__device__ float g_preR[(size_t)NBT*N_*D_];
__device__ float g_preU[(size_t)NBT*N_*D_];
__device__ float g_preC[(size_t)NBT*N_*D_];
__device__ float g_P[N_*N_];                         // P[j][i] = adjI[i][j]
__device__ float g_Q[N_*N_];                         // Q[j][i] = adjI[i][j]*rarW[i][j]

// ---- two-level grid barrier ----
__device__ unsigned int g_cnt[8*32];
__device__ unsigned int g_rootc;
__device__ volatile unsigned int g_gen;

__device__ __forceinline__ void grid_barrier() {
    __syncthreads();
    if (threadIdx.x == 0) {
        __threadfence();
        unsigned int gen = g_gen;
        unsigned int grp = blockIdx.x >> 4;
        unsigned int o = atomicAdd(&g_cnt[grp*32], 1u);
        if ((o & 15u) == 15u) {
            unsigned int r = atomicAdd(&g_rootc, 1u);
            if ((r & 7u) == 7u) {
                __threadfence();
                g_gen = gen + 1u;
            }
        }
        while (g_gen == gen) { }
        __threadfence();
    }
    __syncthreads();
}

__device__ __forceinline__ float tanhfast(float x) {
    float y;
    asm("tanh.approx.f32 %0, %1;" : "=f"(y) : "f"(x));
    return y;
}
__device__ __forceinline__ float sigfast(float x) {
    return fmaf(tanhfast(0.5f*x), 0.5f, 0.5f);
}

__global__ void __launch_bounds__(BLOCK, 1)
cgrnn_persistent(const float* __restrict__ obs,      // [B,T,N,D]
                 const float* __restrict__ mask,     // [B,T,N]
                 const int*   __restrict__ lengths,  // [B]
                 const float* __restrict__ avg,      // [B,T,N]
                 const float* __restrict__ vpe,      // [N,768]
                 const float* __restrict__ rarW,     // [N,N]
                 const float* __restrict__ adjI,     // [N,N]
                 const float* __restrict__ W1,       // [768,128]
                 const float* __restrict__ b1,       // [128]
                 const float* __restrict__ W2,       // [128,5]
                 const float* __restrict__ b2,       // [5]
                 const float* __restrict__ Wr, const float* __restrict__ brp,
                 const float* __restrict__ Wu, const float* __restrict__ bup,
                 const float* __restrict__ Wc, const float* __restrict__ bcp,
                 float* __restrict__ out)            // [B,N,D]
{
    extern __shared__ char smem_raw[];
    float* sm = (float*)smem_raw;
    float* Wst    = sm + OFF_W;
    float* beff_s = sm + OFF_BEFF;
    float* scrU   = sm + U_OFF;
    float* hsB    = sm + HS_OFF;
    const int tid  = threadIdx.x;
    const int bid  = blockIdx.x;
    const int warp = tid >> 5;
    const int lane = tid & 31;
    const int n_node = bid;

    // ========== P1: hypernetwork vv ==========
    {
        float* part = scrU;
        float* hid  = scrU + 1024;
        float* vvs  = scrU + 1152;
        int q = tid >> 7, col = tid & 127;
        const float* vrow = vpe + n_node*768;
        float acc = 0.0f;
        int k0 = q * 96;
        #pragma unroll 4
        for (int k = k0; k < k0 + 96; k++)
            acc = fmaf(vrow[k], W1[k*128 + col], acc);
        part[tid] = acc;
        __syncthreads();
        if (tid < 128) {
            float h = b1[tid];
            #pragma unroll
            for (int qq = 0; qq < 8; qq++) h += part[qq*128 + tid];
            hid[tid] = fmaxf(h, 0.0f);
        }
        __syncthreads();
        if (tid < 5) {
            float a = b2[tid];
            for (int d = 0; d < 128; d++)
                a = fmaf(hid[d], W2[d*5 + tid], a);
            vvs[tid] = a;
        }
        __syncthreads();

        // ===== P2a: effective weights W[g][kk][d], padded k-major =====
        float v0 = vvs[0], v1 = vvs[1], v2 = vvs[2], v3 = vvs[3], v4 = vvs[4];
        __syncthreads();
        for (int idx = tid; idx < 3*KD132; idx += BLOCK) {
            int g  = idx / KD132;
            int kd = idx - g*KD132;
            int kk = kd >> 6;
            int d  = kd & 63;
            float a = 0.0f;
            if (kk < 65 || kk >= 68) {
                int ko = (kk < 65) ? kk : (kk - 3);
                const float* src = (g == 0) ? Wr : (g == 1) ? Wu : Wc;
                int off = ko*64 + d;
                a = v0 * src[off];
                a = fmaf(v1, src[KD + off], a);
                a = fmaf(v2, src[2*KD + off], a);
                a = fmaf(v3, src[3*KD + off], a);
                a = fmaf(v4, src[4*KD + off], a);
            }
            Wst[idx] = a;
        }
        for (int idx = tid; idx < 3*D_; idx += BLOCK) {
            int g = idx >> 6;
            int d = idx & 63;
            const float* src = (g == 0) ? brp : (g == 1) ? bup : bcp;
            float a = v0 * src[d];
            a = fmaf(v1, src[D_ + d], a);
            a = fmaf(v2, src[2*D_ + d], a);
            a = fmaf(v3, src[3*D_ + d], a);
            a = fmaf(v4, src[4*D_ + d], a);
            beff_s[idx] = a;
        }
    }

    // ===== P2b: inv_tot + rs (all t), P/Q transpose, zero h =====
    {
        if (tid < 32) {
            int idx = bid*32 + tid;
            int b = idx >> 7;
            int n = idx & 127;
            float s = 0.0f;
            for (int t = 0; t < T_; t++) s += mask[(b*T_ + t)*N_ + n];
            float inv = 1.0f / (s + 1.0f);
            g_invtot[idx] = inv;
            for (int t = 0; t < T_; t++)
                g_rs[(b*T_ + t)*N_ + n] = 0.5f * tanhfast(avg[(b*T_ + t)*N_ + n] * inv);
        }
        for (int idx = bid*BLOCK + tid; idx < N_*N_; idx += GRID*BLOCK) {
            int j = idx >> 7, i = idx & 127;
            float a = adjI[i*N_ + j];
            g_P[idx] = a;
            g_Q[idx] = a * rarW[i*N_ + j];
        }
        for (int idx = bid*BLOCK + tid; idx < HSZ; idx += GRID*BLOCK)
            g_hbuf[idx] = 0.0f;
        for (int idx = tid; idx < B_*D_; idx += BLOCK) hsB[idx] = 0.0f;
    }
    grid_barrier();

    // ========== A-pre: comb_x for all (b,t) — block=(b,rowhalf,tparity) ==========
    {
        const int b    = bid >> 2;
        const int half = (bid >> 1) & 1;
        const int tpar = bid & 1;
        float* featX = scrU;                 // [128][68]  x|rs|pads
        float* wT2   = scrU + 8704;          // [128][64]
        float* rsv   = scrU + 16896;         // [128]
        int*   list  = (int*)(scrU + 17024); // [128]
        int*   cnt   = (int*)(scrU + 17152); // [8]

        for (int t = tpar; t < T_; t += 2) {
            if (tid < 128) {
                float m = mask[(b*T_ + t)*N_ + tid];
                rsv[tid] = g_rs[(b*T_ + t)*N_ + tid];
                bool ob = (m != 0.0f);
                unsigned msk = __ballot_sync(0xffffffffu, ob);
                if (lane == 0) { cnt[warp] = __popc(msk); ((unsigned*)cnt)[4 + warp] = msk; }
            }
            __syncthreads();
            const int nobs = cnt[0] + cnt[1] + cnt[2] + cnt[3];
            if (tid < 128) {
                unsigned msk = ((unsigned*)cnt)[4 + warp];
                if ((msk >> lane) & 1u) {
                    int off = __popc(msk & ((1u << lane) - 1u));
                    for (int ww = 0; ww < warp; ww++) off += cnt[ww];
                    list[off] = tid;
                }
            }
            __syncthreads();
            const int lo  = (nobs * half) >> 1;
            const int hi  = (nobs * (half + 1)) >> 1;
            const int myn = hi - lo;

            // stage x (cols 0..63), rs (64), pads (65..67)
            for (int idx = tid; idx < nobs*16; idx += BLOCK) {
                int jc = idx >> 4, qq = idx & 15;
                int j = list[jc];
                *(float4*)(featX + jc*68 + qq*4) =
                    *(const float4*)(obs + (size_t)((b*T_ + t)*N_ + j)*D_ + qq*4);
            }
            if (tid < nobs) {
                float* fr = featX + tid*68;
                fr[64] = rsv[list[tid]];
                fr[65] = 0.0f; fr[66] = 0.0f; fr[67] = 0.0f;
            }
            // wT2[jc][ic], ic < myn (<=64)
            {
                int jc0   = warp >> 1;
                int icofs = (warp & 1)*32 + lane;
                int i     = (icofs < myn) ? list[lo + icofs] : 0;
                float rsi = rsv[i];
                bool valid = (icofs < myn);
                for (int jc = jc0; jc < nobs; jc += 16) {
                    int j = list[jc];
                    float wv = 0.0f;
                    if (valid) {
                        if (j == i) wv = 1.0f;
                        else wv = g_P[j*N_ + i] - g_Q[j*N_ + i] * fabsf(rsi - rsv[j]);
                    }
                    wT2[jc*64 + icofs] = wv;
                }
            }
            __syncthreads();

            // GEMM 2row x 2col over 33 col-pairs (cols 0..65)
            const int RG2 = (myn + 1) >> 1;
            for (int tt = tid; tt < RG2*33; tt += BLOCK) {
                int rg = tt / 33;
                int e  = tt - rg*33;
                int c0 = e*2;
                const float* wp = wT2 + rg*2;
                const float* fp = featX + c0;
                float ax = 0.f, ay = 0.f, bx = 0.f, by = 0.f;
                #pragma unroll 4
                for (int jc = 0; jc < nobs; jc++) {
                    float2 w2 = *(const float2*)(wp + jc*64);
                    float2 f2 = *(const float2*)(fp + jc*68);
                    ax = fmaf(w2.x, f2.x, ax); ay = fmaf(w2.x, f2.y, ay);
                    bx = fmaf(w2.y, f2.x, bx); by = fmaf(w2.y, f2.y, by);
                }
                int ic0 = rg*2;
                {
                    int i = list[lo + ic0];
                    *(float2*)&g_combx[((size_t)((b*T_ + t)*N_ + i))*68 + c0] = make_float2(ax, ay);
                }
                if (ic0 + 1 < myn) {
                    int i1 = list[lo + ic0 + 1];
                    *(float2*)&g_combx[((size_t)((b*T_ + t)*N_ + i1))*68 + c0] = make_float2(bx, by);
                }
            }
            __syncthreads();
        }
    }
    grid_barrier();

    // ========== B-pre: gate-x pre-activations for this node ==========
    {
        const int n = n_node;
        int* ptlist = (int*)scrU;            // up to 2048
        int* pcount = (int*)(scrU + 2048);
        if (tid == 0) *pcount = 0;
        __syncthreads();
        for (int pt = tid; pt < NBT; pt += BLOCK) {
            if (mask[pt*N_ + n] != 0.0f) {
                int slot = atomicAdd(pcount, 1);
                ptlist[slot] = pt;
            }
        }
        __syncthreads();
        const int nPT = *pcount;
        const int nq  = (nPT + 3) >> 2;
        const int dgrp = lane >> 1;
        const int ks   = lane & 1;
        const int d0   = dgrp * 4;

        for (int tau = warp; tau < 3*nq; tau += 32) {
            int g    = tau / nq;        // 0=r, 1=u, 2=c
            int quad = tau - g*nq;
            size_t cb[4];
            #pragma unroll
            for (int i = 0; i < 4; i++)
                cb[i] = (size_t)ptlist[min(quad*4 + i, nPT - 1)] * N_ + n;

            float acc[4][4];
            #pragma unroll
            for (int i = 0; i < 4; i++)
                #pragma unroll
                for (int j = 0; j < 4; j++) acc[i][j] = 0.0f;

            const float* Wg = Wst + g*KD132;
            if (g < 2) {
                // over comb_x cols 0..67 (34 pairs), pads zero
                int k2lo = ks ? 17 : 0, k2hi = ks ? 34 : 17;
                const float* p0 = g_combx + cb[0]*68;
                const float* p1 = g_combx + cb[1]*68;
                const float* p2 = g_combx + cb[2]*68;
                const float* p3 = g_combx + cb[3]*68;
                #pragma unroll 2
                for (int k2 = k2lo; k2 < k2hi; k2++) {
                    float2 c0 = *(const float2*)(p0 + 2*k2);
                    float2 c1 = *(const float2*)(p1 + 2*k2);
                    float2 c2 = *(const float2*)(p2 + 2*k2);
                    float2 c3 = *(const float2*)(p3 + 2*k2);
                    float4 wA = *(const float4*)(Wg + (2*k2)*64 + d0);
                    float4 wB = *(const float4*)(Wg + (2*k2 + 1)*64 + d0);
                    acc[0][0] = fmaf(c0.x, wA.x, acc[0][0]); acc[0][0] = fmaf(c0.y, wB.x, acc[0][0]);
                    acc[0][1] = fmaf(c0.x, wA.y, acc[0][1]); acc[0][1] = fmaf(c0.y, wB.y, acc[0][1]);
                    acc[0][2] = fmaf(c0.x, wA.z, acc[0][2]); acc[0][2] = fmaf(c0.y, wB.z, acc[0][2]);
                    acc[0][3] = fmaf(c0.x, wA.w, acc[0][3]); acc[0][3] = fmaf(c0.y, wB.w, acc[0][3]);
                    acc[1][0] = fmaf(c1.x, wA.x, acc[1][0]); acc[1][0] = fmaf(c1.y, wB.x, acc[1][0]);
                    acc[1][1] = fmaf(c1.x, wA.y, acc[1][1]); acc[1][1] = fmaf(c1.y, wB.y, acc[1][1]);
                    acc[1][2] = fmaf(c1.x, wA.z, acc[1][2]); acc[1][2] = fmaf(c1.y, wB.z, acc[1][2]);
                    acc[1][3] = fmaf(c1.x, wA.w, acc[1][3]); acc[1][3] = fmaf(c1.y, wB.w, acc[1][3]);
                    acc[2][0] = fmaf(c2.x, wA.x, acc[2][0]); acc[2][0] = fmaf(c2.y, wB.x, acc[2][0]);
                    acc[2][1] = fmaf(c2.x, wA.y, acc[2][1]); acc[2][1] = fmaf(c2.y, wB.y, acc[2][1]);
                    acc[2][2] = fmaf(c2.x, wA.z, acc[2][2]); acc[2][2] = fmaf(c2.y, wB.z, acc[2][2]);
                    acc[2][3] = fmaf(c2.x, wA.w, acc[2][3]); acc[2][3] = fmaf(c2.y, wB.w, acc[2][3]);
                    acc[3][0] = fmaf(c3.x, wA.x, acc[3][0]); acc[3][0] = fmaf(c3.y, wB.x, acc[3][0]);
                    acc[3][1] = fmaf(c3.x, wA.y, acc[3][1]); acc[3][1] = fmaf(c3.y, wB.y, acc[3][1]);
                    acc[3][2] = fmaf(c3.x, wA.z, acc[3][2]); acc[3][2] = fmaf(c3.y, wB.z, acc[3][2]);
                    acc[3][3] = fmaf(c3.x, wA.w, acc[3][3]); acc[3][3] = fmaf(c3.y, wB.w, acc[3][3]);
                }
            } else {
                // cand-x: raw obs cols 0..63 (32 pairs) + rs term
                int k2lo = ks ? 16 : 0, k2hi = ks ? 32 : 16;
                const float* p0 = obs + cb[0]*64;
                const float* p1 = obs + cb[1]*64;
                const float* p2 = obs + cb[2]*64;
                const float* p3 = obs + cb[3]*64;
                #pragma unroll 2
                for (int k2 = k2lo; k2 < k2hi; k2++) {
                    float2 c0 = *(const float2*)(p0 + 2*k2);
                    float2 c1 = *(const float2*)(p1 + 2*k2);
                    float2 c2 = *(const float2*)(p2 + 2*k2);
                    float2 c3 = *(const float2*)(p3 + 2*k2);
                    float4 wA = *(const float4*)(Wg + (2*k2)*64 + d0);
                    float4 wB = *(const float4*)(Wg + (2*k2 + 1)*64 + d0);
                    acc[0][0] = fmaf(c0.x, wA.x, acc[0][0]); acc[0][0] = fmaf(c0.y, wB.x, acc[0][0]);
                    acc[0][1] = fmaf(c0.x, wA.y, acc[0][1]); acc[0][1] = fmaf(c0.y, wB.y, acc[0][1]);
                    acc[0][2] = fmaf(c0.x, wA.z, acc[0][2]); acc[0][2] = fmaf(c0.y, wB.z, acc[0][2]);
                    acc[0][3] = fmaf(c0.x, wA.w, acc[0][3]); acc[0][3] = fmaf(c0.y, wB.w, acc[0][3]);
                    acc[1][0] = fmaf(c1.x, wA.x, acc[1][0]); acc[1][0] = fmaf(c1.y, wB.x, acc[1][0]);
                    acc[1][1] = fmaf(c1.x, wA.y, acc[1][1]); acc[1][1] = fmaf(c1.y, wB.y, acc[1][1]);
                    acc[1][2] = fmaf(c1.x, wA.z, acc[1][2]); acc[1][2] = fmaf(c1.y, wB.z, acc[1][2]);
                    acc[1][3] = fmaf(c1.x, wA.w, acc[1][3]); acc[1][3] = fmaf(c1.y, wB.w, acc[1][3]);
                    acc[2][0] = fmaf(c2.x, wA.x, acc[2][0]); acc[2][0] = fmaf(c2.y, wB.x, acc[2][0]);
                    acc[2][1] = fmaf(c2.x, wA.y, acc[2][1]); acc[2][1] = fmaf(c2.y, wB.y, acc[2][1]);
                    acc[2][2] = fmaf(c2.x, wA.z, acc[2][2]); acc[2][2] = fmaf(c2.y, wB.z, acc[2][2]);
                    acc[2][3] = fmaf(c2.x, wA.w, acc[2][3]); acc[2][3] = fmaf(c2.y, wB.w, acc[2][3]);
                    acc[3][0] = fmaf(c3.x, wA.x, acc[3][0]); acc[3][0] = fmaf(c3.y, wB.x, acc[3][0]);
                    acc[3][1] = fmaf(c3.x, wA.y, acc[3][1]); acc[3][1] = fmaf(c3.y, wB.y, acc[3][1]);
                    acc[3][2] = fmaf(c3.x, wA.z, acc[3][2]); acc[3][2] = fmaf(c3.y, wB.z, acc[3][2]);
                    acc[3][3] = fmaf(c3.x, wA.w, acc[3][3]); acc[3][3] = fmaf(c3.y, wB.w, acc[3][3]);
                }
            }
            #pragma unroll
            for (int i = 0; i < 4; i++)
                #pragma unroll
                for (int j = 0; j < 4; j++)
                    acc[i][j] += __shfl_xor_sync(0xffffffffu, acc[i][j], 1);

            if (ks == 0) {
                float4 bias = *(const float4*)(beff_s + g*64 + d0);
                float* dst = (g == 0) ? g_preR : (g == 1) ? g_preU : g_preC;
                float4 wrs = *(const float4*)(Wst + 2*KD132 + 64*64 + d0);
                #pragma unroll
                for (int i = 0; i < 4; i++) {
                    float4 v = make_float4(acc[i][0] + bias.x, acc[i][1] + bias.y,
                                           acc[i][2] + bias.z, acc[i][3] + bias.w);
                    if (g == 2) {
                        float rs = g_rs[cb[i]];
                        v.x = fmaf(rs, wrs.x, v.x);
                        v.y = fmaf(rs, wrs.y, v.y);
                        v.z = fmaf(rs, wrs.z, v.z);
                        v.w = fmaf(rs, wrs.w, v.w);
                    }
                    *(float4*)(dst + cb[i]*64 + d0) = v;
                }
            }
        }
    }
    grid_barrier();

    // ========== time loop ==========
    for (int t = 0; t < T_; t++) {
        const float* hprev = g_hbuf + (t & 1) * HSZ;
        float*       hnext = g_hbuf + ((t + 1) & 1) * HSZ;

        // ---------------- Phase A: comb_h only ----------------
        {
            const int b = bid >> 2;
            const int q = bid & 3;
            float* feat = scrU;                  // [128][68], h in cols 0..63
            float* wT   = scrU + 8704;           // [128][32]
            float* rsv  = scrU + 12800;          // [128]
            int*   list = (int*)(scrU + 12928);  // [128]
            int*   cnt  = (int*)(scrU + 13056);  // [8]

            if (tid < 128) {
                float m = mask[(b*T_ + t)*N_ + tid];
                rsv[tid] = g_rs[(b*T_ + t)*N_ + tid];
                bool ob = (m != 0.0f);
                unsigned msk = __ballot_sync(0xffffffffu, ob);
                if (lane == 0) { cnt[warp] = __popc(msk); ((unsigned*)cnt)[4 + warp] = msk; }
            }
            __syncthreads();
            const int nobs = cnt[0] + cnt[1] + cnt[2] + cnt[3];
            if (tid < 128) {
                unsigned msk = ((unsigned*)cnt)[4 + warp];
                if ((msk >> lane) & 1u) {
                    int off = __popc(msk & ((1u << lane) - 1u));
                    for (int ww = 0; ww < warp; ww++) off += cnt[ww];
                    list[off] = tid;
                }
            }
            __syncthreads();
            const int lo  = (nobs * q) >> 2;
            const int hi  = (nobs * (q + 1)) >> 2;
            const int myn = hi - lo;

            for (int idx = tid; idx < nobs*16; idx += BLOCK) {
                int jc = idx >> 4, qq = idx & 15;
                int j = list[jc];
                *(float4*)(feat + jc*68 + qq*4) =
                    *(const float4*)(hprev + (size_t)(b*N_ + j)*D_ + qq*4);
            }
            {
                int jc0 = warp;
                int ic  = lane;
                int i   = (ic < myn) ? list[lo + ic] : 0;
                float rsi = rsv[i];
                bool valid = (ic < myn);
                for (int jc = jc0; jc < nobs; jc += 32) {
                    int j = list[jc];
                    float wv = 0.0f;
                    if (valid) {
                        if (j == i) wv = 1.0f;
                        else wv = g_P[j*N_ + i] - g_Q[j*N_ + i] * fabsf(rsi - rsv[j]);
                    }
                    wT[jc*32 + ic] = wv;
                }
            }
            __syncthreads();

            // GEMM: 1-row x 2-col, tasks = myn*32 <= 1024
            for (int tt = tid; tt < myn*32; tt += BLOCK) {
                int rg = tt >> 5;
                int e  = tt & 31;
                const float* fp = feat + e*2;
                float ax = 0.f, ay = 0.f;
                #pragma unroll 4
                for (int jc = 0; jc < nobs; jc++) {
                    float w  = wT[jc*32 + rg];
                    float2 f2 = *(const float2*)(fp + jc*68);
                    ax = fmaf(w, f2.x, ax);
                    ay = fmaf(w, f2.y, ay);
                }
                int i = list[lo + rg];
                *(float2*)&g_combH[(size_t)(b*N_ + i)*D_ + e*2] = make_float2(ax, ay);
            }
        }
        grid_barrier();

        // ---------------- Phase B: gates over h-part only ----------------
        {
            const int n = n_node;
            float* combH = scrU + 0;              // [32][64]
            float* preR  = scrU + 2048;
            float* preU  = scrU + 4096;
            float* preC  = scrU + 6144;
            float* h1s   = scrU + 8192;
            float* usB   = scrU + 10240;
            int*   listB = (int*)(scrU + 12288);
            int*   listU = (int*)(scrU + 12320);
            int*   lenS  = (int*)(scrU + 12352);
            int*   pnB   = (int*)(scrU + 12384);

            if (tid < 32) {
                int b = tid;
                float m = mask[(b*T_ + t)*N_ + n];
                lenS[b] = lengths[b];
                bool ob = (m != 0.0f);
                unsigned msk = __ballot_sync(0xffffffffu, ob);
                unsigned msku = ~msk;
                if (ob) listB[__popc(msk & ((1u << tid) - 1u))] = b;
                else    listU[__popc(msku & ((1u << tid) - 1u))] = b;
                if (tid == 0) *pnB = __popc(msk);
            }
            __syncthreads();
            const int nB  = *pnB;
            const int BG4 = (nB + 3) >> 2;

            for (int idx = tid; idx < nB*16; idx += BLOCK) {
                int bc = idx >> 4, qq = idx & 15;
                int b  = listB[bc];
                size_t base = ((size_t)((b*T_ + t)*N_ + n))*64 + qq*4;
                *(float4*)(preR + b*64 + qq*4) = *(const float4*)(g_preR + base);
                *(float4*)(preU + b*64 + qq*4) = *(const float4*)(g_preU + base);
                *(float4*)(preC + b*64 + qq*4) = *(const float4*)(g_preC + base);
                *(float4*)(combH + b*64 + qq*4) =
                    *(const float4*)(g_combH + (size_t)(b*N_ + n)*D_ + qq*4);
            }
            __syncthreads();

            const int dgrp = lane >> 1;
            const int ks   = lane & 1;
            const int d0   = dgrp * 4;

            // ---- pass1: warps [0,2*BG4) compute r/u over combH (32 pairs) ----
            if (warp < 2*BG4 && nB > 0) {
                int g    = warp & 1;
                int bgrp = warp >> 1;
                int bb[4];
                #pragma unroll
                for (int i = 0; i < 4; i++) bb[i] = listB[min(bgrp*4 + i, nB - 1)];
                const float* Wg = Wst + g*KD132 + 68*64;   // h rows
                int k2lo = ks ? 16 : 0, k2hi = ks ? 32 : 16;
                float acc[4][4];
                #pragma unroll
                for (int i = 0; i < 4; i++)
                    #pragma unroll
                    for (int j = 0; j < 4; j++) acc[i][j] = 0.0f;
                const float* p0 = combH + bb[0]*64;
                const float* p1 = combH + bb[1]*64;
                const float* p2 = combH + bb[2]*64;
                const float* p3 = combH + bb[3]*64;
                #pragma unroll 2
                for (int k2 = k2lo; k2 < k2hi; k2++) {
                    float2 c0 = *(const float2*)(p0 + 2*k2);
                    float2 c1 = *(const float2*)(p1 + 2*k2);
                    float2 c2 = *(const float2*)(p2 + 2*k2);
                    float2 c3 = *(const float2*)(p3 + 2*k2);
                    float4 wA = *(const float4*)(Wg + (2*k2)*64 + d0);
                    float4 wB = *(const float4*)(Wg + (2*k2 + 1)*64 + d0);
                    acc[0][0] = fmaf(c0.x, wA.x, acc[0][0]); acc[0][0] = fmaf(c0.y, wB.x, acc[0][0]);
                    acc[0][1] = fmaf(c0.x, wA.y, acc[0][1]); acc[0][1] = fmaf(c0.y, wB.y, acc[0][1]);
                    acc[0][2] = fmaf(c0.x, wA.z, acc[0][2]); acc[0][2] = fmaf(c0.y, wB.z, acc[0][2]);
                    acc[0][3] = fmaf(c0.x, wA.w, acc[0][3]); acc[0][3] = fmaf(c0.y, wB.w, acc[0][3]);
                    acc[1][0] = fmaf(c1.x, wA.x, acc[1][0]); acc[1][0] = fmaf(c1.y, wB.x, acc[1][0]);
                    acc[1][1] = fmaf(c1.x, wA.y, acc[1][1]); acc[1][1] = fmaf(c1.y, wB.y, acc[1][1]);
                    acc[1][2] = fmaf(c1.x, wA.z, acc[1][2]); acc[1][2] = fmaf(c1.y, wB.z, acc[1][2]);
                    acc[1][3] = fmaf(c1.x, wA.w, acc[1][3]); acc[1][3] = fmaf(c1.y, wB.w, acc[1][3]);
                    acc[2][0] = fmaf(c2.x, wA.x, acc[2][0]); acc[2][0] = fmaf(c2.y, wB.x, acc[2][0]);
                    acc[2][1] = fmaf(c2.x, wA.y, acc[2][1]); acc[2][1] = fmaf(c2.y, wB.y, acc[2][1]);
                    acc[2][2] = fmaf(c2.x, wA.z, acc[2][2]); acc[2][2] = fmaf(c2.y, wB.z, acc[2][2]);
                    acc[2][3] = fmaf(c2.x, wA.w, acc[2][3]); acc[2][3] = fmaf(c2.y, wB.w, acc[2][3]);
                    acc[3][0] = fmaf(c3.x, wA.x, acc[3][0]); acc[3][0] = fmaf(c3.y, wB.x, acc[3][0]);
                    acc[3][1] = fmaf(c3.x, wA.y, acc[3][1]); acc[3][1] = fmaf(c3.y, wB.y, acc[3][1]);
                    acc[3][2] = fmaf(c3.x, wA.z, acc[3][2]); acc[3][2] = fmaf(c3.y, wB.z, acc[3][2]);
                    acc[3][3] = fmaf(c3.x, wA.w, acc[3][3]); acc[3][3] = fmaf(c3.y, wB.w, acc[3][3]);
                }
                #pragma unroll
                for (int i = 0; i < 4; i++)
                    #pragma unroll
                    for (int j = 0; j < 4; j++)
                        acc[i][j] += __shfl_xor_sync(0xffffffffu, acc[i][j], 1);

                if (ks == 0) {
                    #pragma unroll
                    for (int i = 0; i < 4; i++) {
                        int b = bb[i];
                        if (g == 0) {
                            float4 pr = *(const float4*)(preR + b*64 + d0);
                            float4 h  = *(const float4*)(hsB + b*64 + d0);
                            *(float4*)(h1s + b*64 + d0) = make_float4(
                                sigfast(acc[i][0] + pr.x)*h.x, sigfast(acc[i][1] + pr.y)*h.y,
                                sigfast(acc[i][2] + pr.z)*h.z, sigfast(acc[i][3] + pr.w)*h.w);
                        } else {
                            float4 pu = *(const float4*)(preU + b*64 + d0);
                            *(float4*)(usB + b*64 + d0) = make_float4(
                                sigfast(acc[i][0] + pu.x), sigfast(acc[i][1] + pu.y),
                                sigfast(acc[i][2] + pu.z), sigfast(acc[i][3] + pu.w));
                        }
                    }
                }
            }
            __syncthreads();

            // ---- pass2: candh on warps [0,BG4); carry on the rest ----
            if (warp < BG4 && nB > 0) {
                int bgrp = warp;
                int bb[4];
                #pragma unroll
                for (int i = 0; i < 4; i++) bb[i] = listB[min(bgrp*4 + i, nB - 1)];
                const float* Wg = Wst + 2*KD132 + 68*64;
                int k2lo = ks ? 16 : 0, k2hi = ks ? 32 : 16;
                float acc[4][4];
                #pragma unroll
                for (int i = 0; i < 4; i++)
                    #pragma unroll
                    for (int j = 0; j < 4; j++) acc[i][j] = 0.0f;
                const float* p0 = h1s + bb[0]*64;
                const float* p1 = h1s + bb[1]*64;
                const float* p2 = h1s + bb[2]*64;
                const float* p3 = h1s + bb[3]*64;
                #pragma unroll 2
                for (int k2 = k2lo; k2 < k2hi; k2++) {
                    float2 c0 = *(const float2*)(p0 + 2*k2);
                    float2 c1 = *(const float2*)(p1 + 2*k2);
                    float2 c2 = *(const float2*)(p2 + 2*k2);
                    float2 c3 = *(const float2*)(p3 + 2*k2);
                    float4 wA = *(const float4*)(Wg + (2*k2)*64 + d0);
                    float4 wB = *(const float4*)(Wg + (2*k2 + 1)*64 + d0);
                    acc[0][0] = fmaf(c0.x, wA.x, acc[0][0]); acc[0][0] = fmaf(c0.y, wB.x, acc[0][0]);
                    acc[0][1] = fmaf(c0.x, wA.y, acc[0][1]); acc[0][1] = fmaf(c0.y, wB.y, acc[0][1]);
                    acc[0][2] = fmaf(c0.x, wA.z, acc[0][2]); acc[0][2] = fmaf(c0.y, wB.z, acc[0][2]);
                    acc[0][3] = fmaf(c0.x, wA.w, acc[0][3]); acc[0][3] = fmaf(c0.y, wB.w, acc[0][3]);
                    acc[1][0] = fmaf(c1.x, wA.x, acc[1][0]); acc[1][0] = fmaf(c1.y, wB.x, acc[1][0]);
                    acc[1][1] = fmaf(c1.x, wA.y, acc[1][1]); acc[1][1] = fmaf(c1.y, wB.y, acc[1][1]);
                    acc[1][2] = fmaf(c1.x, wA.z, acc[1][2]); acc[1][2] = fmaf(c1.y, wB.z, acc[1][2]);
                    acc[1][3] = fmaf(c1.x, wA.w, acc[1][3]); acc[1][3] = fmaf(c1.y, wB.w, acc[1][3]);
                    acc[2][0] = fmaf(c2.x, wA.x, acc[2][0]); acc[2][0] = fmaf(c2.y, wB.x, acc[2][0]);
                    acc[2][1] = fmaf(c2.x, wA.y, acc[2][1]); acc[2][1] = fmaf(c2.y, wB.y, acc[2][1]);
                    acc[2][2] = fmaf(c2.x, wA.z, acc[2][2]); acc[2][2] = fmaf(c2.y, wB.z, acc[2][2]);
                    acc[2][3] = fmaf(c2.x, wA.w, acc[2][3]); acc[2][3] = fmaf(c2.y, wB.w, acc[2][3]);
                    acc[3][0] = fmaf(c3.x, wA.x, acc[3][0]); acc[3][0] = fmaf(c3.y, wB.x, acc[3][0]);
                    acc[3][1] = fmaf(c3.x, wA.y, acc[3][1]); acc[3][1] = fmaf(c3.y, wB.y, acc[3][1]);
                    acc[3][2] = fmaf(c3.x, wA.z, acc[3][2]); acc[3][2] = fmaf(c3.y, wB.z, acc[3][2]);
                    acc[3][3] = fmaf(c3.x, wA.w, acc[3][3]); acc[3][3] = fmaf(c3.y, wB.w, acc[3][3]);
                }
                #pragma unroll
                for (int i = 0; i < 4; i++)
                    #pragma unroll
                    for (int j = 0; j < 4; j++)
                        acc[i][j] += __shfl_xor_sync(0xffffffffu, acc[i][j], 1);

                if (ks == 0) {
                    #pragma unroll
                    for (int i = 0; i < 4; i++) {
                        int b = bb[i];
                        float4 pc = *(const float4*)(preC + b*64 + d0);
                        float4 h1 = *(const float4*)(h1s + b*64 + d0);
                        float4 u  = *(const float4*)(usB + b*64 + d0);
                        float4 v;
                        v.x = h1.x + u.x*(tanhfast(acc[i][0] + pc.x) - h1.x);
                        v.y = h1.y + u.y*(tanhfast(acc[i][1] + pc.y) - h1.y);
                        v.z = h1.z + u.z*(tanhfast(acc[i][2] + pc.z) - h1.z);
                        v.w = h1.w + u.w*(tanhfast(acc[i][3] + pc.w) - h1.w);
                        *(float4*)(hnext + (size_t)(b*N_ + n)*D_ + d0) = v;
                        *(float4*)(hsB + b*64 + d0) = v;
                        if (t == lenS[b] - 1)
                            *(float4*)(out + (size_t)(b*N_ + n)*D_ + d0) = v;
                    }
                }
            } else if (warp >= BG4) {
                int w2 = warp - BG4;
                int nU = B_ - nB;
                int pairs = (nU + 1) >> 1;
                if (w2 < pairs) {
                    int iu = w2 * 2;
                    int dd = lane * 2;
                    #pragma unroll
                    for (int rep = 0; rep < 2; rep++) {
                        if (iu + rep < nU) {
                            int b = listU[iu + rep];
                            float2 v = *(const float2*)(hsB + b*64 + dd);
                            *(float2*)(hnext + (size_t)(b*N_ + n)*D_ + dd) = v;
                            if (t == lenS[b] - 1)
                                *(float2*)(out + (size_t)(b*N_ + n)*D_ + dd) = v;
                        }
                    }
                }
            }
        }
        grid_barrier();
    }
}

extern "C" void kernel_launch(void* const* d_in, const int* in_sizes, int n_in,
                              void* d_out, int out_size) {
    const float* obs     = (const float*)d_in[0];
    const float* mask    = (const float*)d_in[2];
    const int*   lengths = (const int*)d_in[5];
    const float* avg     = (const float*)d_in[6];
    const float* vpe     = (const float*)d_in[7];
    const float* rarW    = (const float*)d_in[8];
    const float* adjI    = (const float*)d_in[9];
    const float* W1      = (const float*)d_in[10];
    const float* b1      = (const float*)d_in[11];
    const float* W2      = (const float*)d_in[12];
    const float* b2      = (const float*)d_in[13];
    const float* Wu      = (const float*)d_in[14];
    const float* bu      = (const float*)d_in[15];
    const float* Wr      = (const float*)d_in[16];
    const float* br      = (const float*)d_in[17];
    const float* Wc      = (const float*)d_in[18];
    const float* bc      = (const float*)d_in[19];
    float* out = (float*)d_out;

    cudaFuncSetAttribute(cgrnn_persistent,
                         cudaFuncAttributeMaxDynamicSharedMemorySize, SMEM_BYTES);
    cgrnn_persistent<<<GRID, BLOCK, SMEM_BYTES>>>(
        obs, mask, lengths, avg, vpe, rarW, adjI,
        W1, b1, W2, b2, Wr, br, Wu, bu, Wc, bc, out);
}

// round 14
// speedup vs baseline: 1.1534x; 1.1534x over previous
#include <cuda_runtime.h>
#include <cuda_bf16.h>
#include <math.h>

#define B_ 32
#define T_ 64
#define N_ 128
#define D_ 64
#define K2 129
#define KD (K2*D_)
#define KR 132              // [x 0..63 | rs 64 | pad 65..67 | h 68..131]
#define KD132 (KR*D_)
#define HSZ (B_*N_*D_)
#define GRID 128
#define BLOCK 1024

// ---- smem layout (floats) ----
#define OFF_W     0                    // 3*KD132 (W[g][k][d], k-major)
#define OFF_BEFF  (3*KD132)            // 192
#define U_OFF     (3*KD132 + 192)      // union scratch
#define U_SIZE    21256
#define HS_OFF    (U_OFF + U_SIZE)     // persistent h [32][64]
#define ZCS_OFF   (HS_OFF + 2048)      // persistent zcs [32][132]
#define LB_OFF    (ZCS_OFF + 4224)     // persistent lists: listB(32) listU(32) lenS(32) pnB(4)
#define SMEM_FLOATS (LB_OFF + 100)
#define SMEM_BYTES  (SMEM_FLOATS*4 + 64)

__device__ float g_invtot[B_*N_];
__device__ float g_hbuf[2*HSZ];
__device__ float g_comb[B_*N_*KR];
__device__ float g_P[N_*N_];
__device__ float g_Q[N_*N_];

__device__ unsigned int g_cnt[8*32];
__device__ unsigned int g_rootc;
__device__ volatile unsigned int g_gen;

__device__ __forceinline__ void grid_barrier() {
    __syncthreads();
    if (threadIdx.x == 0) {
        __threadfence();
        unsigned int gen = g_gen;
        unsigned int grp = blockIdx.x >> 4;
        unsigned int o = atomicAdd(&g_cnt[grp*32], 1u);
        if ((o & 15u) == 15u) {
            unsigned int r = atomicAdd(&g_rootc, 1u);
            if ((r & 7u) == 7u) {
                __threadfence();
                g_gen = gen + 1u;
            }
        }
        while (g_gen == gen) { }
        __threadfence();
    }
    __syncthreads();
}

__device__ __forceinline__ float tanhfast(float x) {
    float y;
    asm("tanh.approx.f32 %0, %1;" : "=f"(y) : "f"(x));
    return y;
}
__device__ __forceinline__ float sigfast(float x) {
    return fmaf(tanhfast(0.5f*x), 0.5f, 0.5f);
}

__global__ void __launch_bounds__(BLOCK, 1)
cgrnn_persistent(const float* __restrict__ obs,
                 const float* __restrict__ mask,
                 const int*   __restrict__ lengths,
                 const float* __restrict__ avg,
                 const float* __restrict__ vpe,
                 const float* __restrict__ rarW,
                 const float* __restrict__ adjI,
                 const float* __restrict__ W1,
                 const float* __restrict__ b1,
                 const float* __restrict__ W2,
                 const float* __restrict__ b2,
                 const float* __restrict__ Wr, const float* __restrict__ brp,
                 const float* __restrict__ Wu, const float* __restrict__ bup,
                 const float* __restrict__ Wc, const float* __restrict__ bcp,
                 float* __restrict__ out)
{
    extern __shared__ char smem_raw[];
    float* sm = (float*)smem_raw;
    float* Wst    = sm + OFF_W;
    float* beff_s = sm + OFF_BEFF;
    float* scrU   = sm + U_OFF;
    float* hsB    = sm + HS_OFF;
    float* zcs    = sm + ZCS_OFF;
    int*   listB  = (int*)(sm + LB_OFF);
    int*   listU  = (int*)(sm + LB_OFF + 32);
    int*   lenS   = (int*)(sm + LB_OFF + 64);
    int*   pnB    = (int*)(sm + LB_OFF + 96);
    const int tid  = threadIdx.x;
    const int bid  = blockIdx.x;
    const int warp = tid >> 5;
    const int lane = tid & 31;
    const int n_node = bid;

    float* combs = scrU + 0;
    float* usB   = scrU + 4224;
    float* cxsB  = scrU + 6272;

    // ========== P1: hypernetwork vv ==========
    {
        float* part = scrU;
        float* hid  = scrU + 1024;
        float* vvs  = scrU + 1152;
        int q = tid >> 7, col = tid & 127;
        const float* vrow = vpe + n_node*768;
        float acc = 0.0f;
        int k0 = q * 96;
        #pragma unroll 4
        for (int k = k0; k < k0 + 96; k++)
            acc = fmaf(vrow[k], W1[k*128 + col], acc);
        part[tid] = acc;
        __syncthreads();
        if (tid < 128) {
            float h = b1[tid];
            #pragma unroll
            for (int qq = 0; qq < 8; qq++) h += part[qq*128 + tid];
            hid[tid] = fmaxf(h, 0.0f);
        }
        __syncthreads();
        if (tid < 5) {
            float a = b2[tid];
            for (int d = 0; d < 128; d++)
                a = fmaf(hid[d], W2[d*5 + tid], a);
            vvs[tid] = a;
        }
        __syncthreads();

        float v0 = vvs[0], v1 = vvs[1], v2 = vvs[2], v3 = vvs[3], v4 = vvs[4];
        __syncthreads();
        for (int idx = tid; idx < 3*KD132; idx += BLOCK) {
            int g  = idx / KD132;
            int kd = idx - g*KD132;
            int kk = kd >> 6;
            int d  = kd & 63;
            float a = 0.0f;
            if (kk < 65 || kk >= 68) {
                int ko = (kk < 65) ? kk : (kk - 3);
                const float* src = (g == 0) ? Wr : (g == 1) ? Wu : Wc;
                int off = ko*64 + d;
                a = v0 * src[off];
                a = fmaf(v1, src[KD + off], a);
                a = fmaf(v2, src[2*KD + off], a);
                a = fmaf(v3, src[3*KD + off], a);
                a = fmaf(v4, src[4*KD + off], a);
            }
            Wst[idx] = a;
        }
        for (int idx = tid; idx < 3*D_; idx += BLOCK) {
            int g = idx >> 6;
            int d = idx & 63;
            const float* src = (g == 0) ? brp : (g == 1) ? bup : bcp;
            float a = v0 * src[d];
            a = fmaf(v1, src[D_ + d], a);
            a = fmaf(v2, src[2*D_ + d], a);
            a = fmaf(v3, src[3*D_ + d], a);
            a = fmaf(v4, src[4*D_ + d], a);
            beff_s[idx] = a;
        }
    }

    // ===== P2b: inv_tot, P/Q, zero h, persistent init =====
    {
        for (int k = tid; k < 32; k += BLOCK) {
            int idx = bid*32 + k;
            int b = idx >> 7;
            int n = idx & 127;
            float s = 0.0f;
            for (int t = 0; t < T_; t++) s += mask[(b*T_ + t)*N_ + n];
            g_invtot[idx] = 1.0f / (s + 1.0f);
        }
        for (int idx = bid*BLOCK + tid; idx < N_*N_; idx += GRID*BLOCK) {
            int j = idx >> 7, i = idx & 127;
            float a = adjI[i*N_ + j];
            g_P[idx] = a;
            g_Q[idx] = a * rarW[i*N_ + j];
        }
        for (int idx = bid*BLOCK + tid; idx < HSZ; idx += GRID*BLOCK)
            g_hbuf[idx] = 0.0f;
        for (int idx = tid; idx < B_*D_; idx += BLOCK) hsB[idx] = 0.0f;
        for (int idx = tid; idx < B_*16; idx += BLOCK) {
            int b = idx >> 4, qq = idx & 15;
            *(float4*)(zcs + b*KR + qq*4) =
                *(const float4*)(obs + (size_t)((b*T_)*N_ + n_node)*D_ + qq*4);
        }
        if (tid < 32) {
            float* zr = zcs + tid*KR;
            zr[65] = 0.0f; zr[66] = 0.0f; zr[67] = 0.0f;
            lenS[tid] = lengths[tid];
        }
    }
    grid_barrier();
    if (tid < 32) {
        zcs[tid*KR + 64] =
            0.5f * tanhfast(avg[(tid*T_)*N_ + n_node] * g_invtot[tid*N_ + n_node]);
    }
    __syncthreads();

    // Phase A scratch aliases
    float* feat = scrU + 0;              // [128][132]
    float* wT   = scrU + 16896;          // [128][32]
    float* rsv  = scrU + 20992;          // [128]
    int*   list = (int*)(scrU + 21120);  // [128]
    int*   cnt  = (int*)(scrU + 21248);  // [8]

    // ========== time loop ==========
    for (int t = 0; t < T_; t++) {
        const float* hprev = g_hbuf + (t & 1) * HSZ;
        float*       hnext = g_hbuf + ((t + 1) & 1) * HSZ;
        const int b = bid >> 2;
        const int q = bid & 3;

        // ---- A-setup (h-independent) — runs BEFORE barrier 1 ----
        if (tid < 128) {
            float m = mask[(b*T_ + t)*N_ + tid];
            rsv[tid] = 0.5f * tanhfast(avg[(b*T_ + t)*N_ + tid] * g_invtot[b*N_ + tid]);
            bool ob = (m != 0.0f);
            unsigned msk = __ballot_sync(0xffffffffu, ob);
            if (lane == 0) { cnt[warp] = __popc(msk); ((unsigned*)cnt)[4 + warp] = msk; }
        }
        // Phase-B lists for this node at step t (mask-only)
        if (tid >= 128 && tid < 160) {
            int bb = tid - 128;
            float m = mask[(bb*T_ + t)*N_ + n_node];
            bool ob = (m != 0.0f);
            unsigned msk = __ballot_sync(0xffffffffu, ob);
            unsigned msku = ~msk;
            int l = bb;
            if (ob) listB[__popc(msk & ((1u << l) - 1u))] = bb;
            else    listU[__popc(msku & ((1u << l) - 1u))] = bb;
            if (l == 0) *pnB = __popc(msk);
        }
        __syncthreads();
        const int nobs = cnt[0] + cnt[1] + cnt[2] + cnt[3];
        if (tid < 128) {
            unsigned msk = ((unsigned*)cnt)[4 + warp];
            if ((msk >> lane) & 1u) {
                int off = __popc(msk & ((1u << lane) - 1u));
                for (int ww = 0; ww < warp; ww++) off += cnt[ww];
                list[off] = tid;
            }
        }
        __syncthreads();

        const int lo  = (nobs * q) >> 2;
        const int hi  = (nobs * (q + 1)) >> 2;
        const int myn = hi - lo;

        // feat x|rs|pads (h-independent)
        for (int idx = tid; idx < nobs*16; idx += BLOCK) {
            int jc = idx >> 4, qq = idx & 15;
            int j = list[jc];
            *(float4*)(feat + jc*KR + qq*4) =
                *(const float4*)(obs + (size_t)((b*T_ + t)*N_ + j)*D_ + qq*4);
        }
        if (tid < nobs) {
            float* fr = feat + tid*KR;
            fr[64] = rsv[list[tid]];
            fr[65] = 0.0f; fr[66] = 0.0f; fr[67] = 0.0f;
        }
        // wT staging (h-independent)
        {
            int jc0 = warp;
            int ic  = lane;
            int i   = (ic < myn) ? list[lo + ic] : 0;
            float rsi = rsv[i];
            bool valid = (ic < myn);
            for (int jc = jc0; jc < nobs; jc += 32) {
                int j = list[jc];
                float wv = 0.0f;
                if (valid) {
                    if (j == i) wv = 1.0f;
                    else wv = g_P[j*N_ + i] - g_Q[j*N_ + i] * fabsf(rsi - rsv[j]);
                }
                wT[jc*32 + ic] = wv;
            }
        }

        grid_barrier();   // wait for all blocks' h(t) writes

        // ---- feat-h staging + GEMM ----
        for (int idx = tid; idx < nobs*16; idx += BLOCK) {
            int jc = idx >> 4, qq = idx & 15;
            int j = list[jc];
            *(float4*)(feat + jc*KR + 68 + qq*4) =
                *(const float4*)(hprev + (size_t)(b*N_ + j)*D_ + qq*4);
        }
        __syncthreads();

        const int RG2 = (myn + 1) >> 1;
        for (int tt = tid; tt < RG2*66; tt += BLOCK) {
            int rg = tt / 66;
            int e  = tt - rg*66;
            int c0 = e*2;
            const float* wp = wT + rg*2;
            const float* fp = feat + c0;
            float ax = 0.f, ay = 0.f, bx = 0.f, by = 0.f;
            #pragma unroll 4
            for (int jc = 0; jc < nobs; jc++) {
                float2 w2 = *(const float2*)(wp + jc*32);
                float2 f2 = *(const float2*)(fp + jc*KR);
                ax = fmaf(w2.x, f2.x, ax); ay = fmaf(w2.x, f2.y, ay);
                bx = fmaf(w2.y, f2.x, bx); by = fmaf(w2.y, f2.y, by);
            }
            int ic0 = rg*2;
            {
                int i = list[lo + ic0];
                *(float2*)&g_comb[(size_t)(b*N_ + i)*KR + c0] = make_float2(ax, ay);
            }
            if (ic0 + 1 < myn) {
                int i1 = list[lo + ic0 + 1];
                *(float2*)&g_comb[(size_t)(b*N_ + i1)*KR + c0] = make_float2(bx, by);
            }
        }

        grid_barrier();   // g_comb ready

        // ---------------- Phase B ----------------
        {
            const int n = n_node;
            const int nB  = *pnB;
            const int BG4 = (nB + 3) >> 2;

            for (int idx = tid; idx < nB*33; idx += BLOCK) {
                int bc = idx / 33;
                int qq = idx - bc*33;
                int bb = listB[bc];
                *(float4*)(combs + bb*KR + qq*4) =
                    *(const float4*)(g_comb + (size_t)(bb*N_ + n)*KR + qq*4);
            }
            __syncthreads();

            const int dgrp = lane >> 1;
            const int ks   = lane & 1;
            const int d0   = dgrp * 4;

            // ---- pass1: warps [0,2*BG4) r/u; [2*BG4,3*BG4) candx ----
            if (warp < 3*BG4 && nB > 0) {
                int isRU = (warp < 2*BG4);
                int g, bgrp;
                const float* cbase;
                int k2lo, k2hi;
                if (isRU) {
                    g = warp & 1; bgrp = warp >> 1;
                    cbase = combs;
                    k2lo = ks ? 33 : 0;  k2hi = ks ? 66 : 33;
                } else {
                    g = 2; bgrp = warp - 2*BG4;
                    cbase = zcs;
                    k2lo = ks ? 17 : 0;  k2hi = ks ? 34 : 17;
                }
                int bb[4];
                #pragma unroll
                for (int i = 0; i < 4; i++) bb[i] = listB[min(bgrp*4 + i, nB - 1)];
                const float* Wg = Wst + g*KD132;
                float acc[4][4];
                #pragma unroll
                for (int i = 0; i < 4; i++)
                    #pragma unroll
                    for (int j = 0; j < 4; j++) acc[i][j] = 0.0f;

                const float* c0p = cbase + bb[0]*KR;
                const float* c1p = cbase + bb[1]*KR;
                const float* c2p = cbase + bb[2]*KR;
                const float* c3p = cbase + bb[3]*KR;
                #pragma unroll 2
                for (int k2 = k2lo; k2 < k2hi; k2++) {
                    float2 c0 = *(const float2*)(c0p + 2*k2);
                    float2 c1 = *(const float2*)(c1p + 2*k2);
                    float2 c2 = *(const float2*)(c2p + 2*k2);
                    float2 c3 = *(const float2*)(c3p + 2*k2);
                    float4 wA = *(const float4*)(Wg + (2*k2)*64 + d0);
                    float4 wB = *(const float4*)(Wg + (2*k2 + 1)*64 + d0);
                    acc[0][0] = fmaf(c0.x, wA.x, acc[0][0]); acc[0][0] = fmaf(c0.y, wB.x, acc[0][0]);
                    acc[0][1] = fmaf(c0.x, wA.y, acc[0][1]); acc[0][1] = fmaf(c0.y, wB.y, acc[0][1]);
                    acc[0][2] = fmaf(c0.x, wA.z, acc[0][2]); acc[0][2] = fmaf(c0.y, wB.z, acc[0][2]);
                    acc[0][3] = fmaf(c0.x, wA.w, acc[0][3]); acc[0][3] = fmaf(c0.y, wB.w, acc[0][3]);
                    acc[1][0] = fmaf(c1.x, wA.x, acc[1][0]); acc[1][0] = fmaf(c1.y, wB.x, acc[1][0]);
                    acc[1][1] = fmaf(c1.x, wA.y, acc[1][1]); acc[1][1] = fmaf(c1.y, wB.y, acc[1][1]);
                    acc[1][2] = fmaf(c1.x, wA.z, acc[1][2]); acc[1][2] = fmaf(c1.y, wB.z, acc[1][2]);
                    acc[1][3] = fmaf(c1.x, wA.w, acc[1][3]); acc[1][3] = fmaf(c1.y, wB.w, acc[1][3]);
                    acc[2][0] = fmaf(c2.x, wA.x, acc[2][0]); acc[2][0] = fmaf(c2.y, wB.x, acc[2][0]);
                    acc[2][1] = fmaf(c2.x, wA.y, acc[2][1]); acc[2][1] = fmaf(c2.y, wB.y, acc[2][1]);
                    acc[2][2] = fmaf(c2.x, wA.z, acc[2][2]); acc[2][2] = fmaf(c2.y, wB.z, acc[2][2]);
                    acc[2][3] = fmaf(c2.x, wA.w, acc[2][3]); acc[2][3] = fmaf(c2.y, wB.w, acc[2][3]);
                    acc[3][0] = fmaf(c3.x, wA.x, acc[3][0]); acc[3][0] = fmaf(c3.y, wB.x, acc[3][0]);
                    acc[3][1] = fmaf(c3.x, wA.y, acc[3][1]); acc[3][1] = fmaf(c3.y, wB.y, acc[3][1]);
                    acc[3][2] = fmaf(c3.x, wA.z, acc[3][2]); acc[3][2] = fmaf(c3.y, wB.z, acc[3][2]);
                    acc[3][3] = fmaf(c3.x, wA.w, acc[3][3]); acc[3][3] = fmaf(c3.y, wB.w, acc[3][3]);
                }
                #pragma unroll
                for (int i = 0; i < 4; i++)
                    #pragma unroll
                    for (int j = 0; j < 4; j++)
                        acc[i][j] += __shfl_xor_sync(0xffffffffu, acc[i][j], 1);

                if (ks == 0) {
                    float4 bias = *(const float4*)(beff_s + g*64 + d0);
                    #pragma unroll
                    for (int i = 0; i < 4; i++) {
                        int bb2 = bb[i];
                        float4 v = make_float4(acc[i][0] + bias.x, acc[i][1] + bias.y,
                                               acc[i][2] + bias.z, acc[i][3] + bias.w);
                        if (g == 0) {
                            float4 h = *(const float4*)(hsB + bb2*64 + d0);
                            *(float4*)(zcs + bb2*KR + 68 + d0) =
                                make_float4(sigfast(v.x)*h.x, sigfast(v.y)*h.y,
                                            sigfast(v.z)*h.z, sigfast(v.w)*h.w);
                        } else if (g == 1) {
                            *(float4*)(usB + bb2*64 + d0) =
                                make_float4(sigfast(v.x), sigfast(v.y),
                                            sigfast(v.z), sigfast(v.w));
                        } else {
                            *(float4*)(cxsB + bb2*64 + d0) = v;
                        }
                    }
                }
            }
            __syncthreads();

            // ---- pass2: candh warps [0,BG4); carry on the rest ----
            if (warp < BG4 && nB > 0) {
                int bgrp = warp;
                int bb[4];
                #pragma unroll
                for (int i = 0; i < 4; i++) bb[i] = listB[min(bgrp*4 + i, nB - 1)];
                const float* Wg = Wst + 2*KD132;
                int k2lo = ks ? 50 : 34;
                int k2hi = ks ? 66 : 50;
                float acc[4][4];
                #pragma unroll
                for (int i = 0; i < 4; i++)
                    #pragma unroll
                    for (int j = 0; j < 4; j++) acc[i][j] = 0.0f;
                const float* c0p = zcs + bb[0]*KR;
                const float* c1p = zcs + bb[1]*KR;
                const float* c2p = zcs + bb[2]*KR;
                const float* c3p = zcs + bb[3]*KR;
                #pragma unroll 2
                for (int k2 = k2lo; k2 < k2hi; k2++) {
                    float2 c0 = *(const float2*)(c0p + 2*k2);
                    float2 c1 = *(const float2*)(c1p + 2*k2);
                    float2 c2 = *(const float2*)(c2p + 2*k2);
                    float2 c3 = *(const float2*)(c3p + 2*k2);
                    float4 wA = *(const float4*)(Wg + (2*k2)*64 + d0);
                    float4 wB = *(const float4*)(Wg + (2*k2 + 1)*64 + d0);
                    acc[0][0] = fmaf(c0.x, wA.x, acc[0][0]); acc[0][0] = fmaf(c0.y, wB.x, acc[0][0]);
                    acc[0][1] = fmaf(c0.x, wA.y, acc[0][1]); acc[0][1] = fmaf(c0.y, wB.y, acc[0][1]);
                    acc[0][2] = fmaf(c0.x, wA.z, acc[0][2]); acc[0][2] = fmaf(c0.y, wB.z, acc[0][2]);
                    acc[0][3] = fmaf(c0.x, wA.w, acc[0][3]); acc[0][3] = fmaf(c0.y, wB.w, acc[0][3]);
                    acc[1][0] = fmaf(c1.x, wA.x, acc[1][0]); acc[1][0] = fmaf(c1.y, wB.x, acc[1][0]);
                    acc[1][1] = fmaf(c1.x, wA.y, acc[1][1]); acc[1][1] = fmaf(c1.y, wB.y, acc[1][1]);
                    acc[1][2] = fmaf(c1.x, wA.z, acc[1][2]); acc[1][2] = fmaf(c1.y, wB.z, acc[1][2]);
                    acc[1][3] = fmaf(c1.x, wA.w, acc[1][3]); acc[1][3] = fmaf(c1.y, wB.w, acc[1][3]);
                    acc[2][0] = fmaf(c2.x, wA.x, acc[2][0]); acc[2][0] = fmaf(c2.y, wB.x, acc[2][0]);
                    acc[2][1] = fmaf(c2.x, wA.y, acc[2][1]); acc[2][1] = fmaf(c2.y, wB.y, acc[2][1]);
                    acc[2][2] = fmaf(c2.x, wA.z, acc[2][2]); acc[2][2] = fmaf(c2.y, wB.z, acc[2][2]);
                    acc[2][3] = fmaf(c2.x, wA.w, acc[2][3]); acc[2][3] = fmaf(c2.y, wB.w, acc[2][3]);
                    acc[3][0] = fmaf(c3.x, wA.x, acc[3][0]); acc[3][0] = fmaf(c3.y, wB.x, acc[3][0]);
                    acc[3][1] = fmaf(c3.x, wA.y, acc[3][1]); acc[3][1] = fmaf(c3.y, wB.y, acc[3][1]);
                    acc[3][2] = fmaf(c3.x, wA.z, acc[3][2]); acc[3][2] = fmaf(c3.y, wB.z, acc[3][2]);
                    acc[3][3] = fmaf(c3.x, wA.w, acc[3][3]); acc[3][3] = fmaf(c3.y, wB.w, acc[3][3]);
                }
                #pragma unroll
                for (int i = 0; i < 4; i++)
                    #pragma unroll
                    for (int j = 0; j < 4; j++)
                        acc[i][j] += __shfl_xor_sync(0xffffffffu, acc[i][j], 1);

                if (ks == 0) {
                    #pragma unroll
                    for (int i = 0; i < 4; i++) {
                        int bb2 = bb[i];
                        float4 cx = *(const float4*)(cxsB + bb2*64 + d0);
                        float4 h1 = *(const float4*)(zcs + bb2*KR + 68 + d0);
                        float4 u  = *(const float4*)(usB + bb2*64 + d0);
                        float4 v;
                        v.x = h1.x + u.x*(tanhfast(acc[i][0] + cx.x) - h1.x);
                        v.y = h1.y + u.y*(tanhfast(acc[i][1] + cx.y) - h1.y);
                        v.z = h1.z + u.z*(tanhfast(acc[i][2] + cx.z) - h1.z);
                        v.w = h1.w + u.w*(tanhfast(acc[i][3] + cx.w) - h1.w);
                        *(float4*)(hnext + (size_t)(bb2*N_ + n)*D_ + d0) = v;
                        *(float4*)(hsB + bb2*64 + d0) = v;
                        if (t == lenS[bb2] - 1)
                            *(float4*)(out + (size_t)(bb2*N_ + n)*D_ + d0) = v;
                    }
                }
            } else if (warp >= BG4) {
                int w2 = warp - BG4;
                int nU = B_ - nB;
                int pairs = (nU + 1) >> 1;
                if (w2 < pairs) {
                    int iu = w2 * 2;
                    int dd = lane * 2;
                    #pragma unroll
                    for (int rep = 0; rep < 2; rep++) {
                        if (iu + rep < nU) {
                            int bb2 = listU[iu + rep];
                            float2 v = *(const float2*)(hsB + bb2*64 + dd);
                            *(float2*)(hnext + (size_t)(bb2*N_ + n)*D_ + dd) = v;
                            if (t == lenS[bb2] - 1)
                                *(float2*)(out + (size_t)(bb2*N_ + n)*D_ + dd) = v;
                        }
                    }
                }
            }
            // prefetch next step zcs x + rs
            if (t + 1 < T_) {
                for (int idx = tid; idx < B_*16; idx += BLOCK) {
                    int bb2 = idx >> 4, qq = idx & 15;
                    *(float4*)(zcs + bb2*KR + qq*4) =
                        *(const float4*)(obs + (size_t)((bb2*T_ + t + 1)*N_ + n)*D_ + qq*4);
                }
                if (tid < 32) {
                    zcs[tid*KR + 64] =
                        0.5f * tanhfast(avg[(tid*T_ + t + 1)*N_ + n] * g_invtot[tid*N_ + n]);
                }
            }
        }
        __syncthreads();   // protect scrU reuse by next iteration's A-setup
    }
}

extern "C" void kernel_launch(void* const* d_in, const int* in_sizes, int n_in,
                              void* d_out, int out_size) {
    const float* obs     = (const float*)d_in[0];
    const float* mask    = (const float*)d_in[2];
    const int*   lengths = (const int*)d_in[5];
    const float* avg     = (const float*)d_in[6];
    const float* vpe     = (const float*)d_in[7];
    const float* rarW    = (const float*)d_in[8];
    const float* adjI    = (const float*)d_in[9];
    const float* W1      = (const float*)d_in[10];
    const float* b1      = (const float*)d_in[11];
    const float* W2      = (const float*)d_in[12];
    const float* b2      = (const float*)d_in[13];
    const float* Wu      = (const float*)d_in[14];
    const float* bu      = (const float*)d_in[15];
    const float* Wr      = (const float*)d_in[16];
    const float* br      = (const float*)d_in[17];
    const float* Wc      = (const float*)d_in[18];
    const float* bc      = (const float*)d_in[19];
    float* out = (float*)d_out;

    cudaFuncSetAttribute(cgrnn_persistent,
                         cudaFuncAttributeMaxDynamicSharedMemorySize, SMEM_BYTES);
    cgrnn_persistent<<<GRID, BLOCK, SMEM_BYTES>>>(
        obs, mask, lengths, avg, vpe, rarW, adjI,
        W1, b1, W2, b2, Wr, br, Wu, bu, Wc, bc, out);
}

// round 15
// speedup vs baseline: 1.1542x; 1.0007x over previous
#include <cuda_runtime.h>
#include <cuda_bf16.h>
#include <math.h>

#define B_ 32
#define T_ 64
#define N_ 128
#define D_ 64
#define K2 129
#define KD (K2*D_)
#define KR 132              // [x 0..63 | rs 64 | pad 65..67 | h 68..131]
#define KD132 (KR*D_)
#define HSZ (B_*N_*D_)
#define GRID 128
#define BLOCK 1024

// ---- smem layout (floats) ----
#define OFF_W     0                    // 3*KD132 (W[g][k][d], k-major)
#define OFF_BEFF  (3*KD132)            // 192
#define U_OFF     (3*KD132 + 192)      // union scratch
#define U_SIZE    21256
#define HS_OFF    (U_OFF + U_SIZE)     // persistent h [32][64]
#define ZCS_OFF   (HS_OFF + 2048)      // persistent zcs [32][132]
#define LB_OFF    (ZCS_OFF + 4224)     // lists: listB(32) listU(32) lenS(32) pnB(4)
#define CX_OFF    (LB_OFF + 128)       // persistent cxsB [32][64]
#define SMEM_FLOATS (CX_OFF + 2048)
#define SMEM_BYTES  (SMEM_FLOATS*4 + 64)

__device__ float g_invtot[B_*N_];
__device__ float g_hbuf[2*HSZ];
__device__ float g_comb[B_*N_*KR];
__device__ float g_P[N_*N_];
__device__ float g_Q[N_*N_];

__device__ unsigned int g_cnt[8*32];
__device__ unsigned int g_rootc;
__device__ volatile unsigned int g_gen;

__device__ __forceinline__ void grid_barrier() {
    __syncthreads();
    if (threadIdx.x == 0) {
        __threadfence();
        unsigned int gen = g_gen;
        unsigned int grp = blockIdx.x >> 4;
        unsigned int o = atomicAdd(&g_cnt[grp*32], 1u);
        if ((o & 15u) == 15u) {
            unsigned int r = atomicAdd(&g_rootc, 1u);
            if ((r & 7u) == 7u) {
                __threadfence();
                g_gen = gen + 1u;
            }
        }
        while (g_gen == gen) { }
        __threadfence();
    }
    __syncthreads();
}

__device__ __forceinline__ float tanhfast(float x) {
    float y;
    asm("tanh.approx.f32 %0, %1;" : "=f"(y) : "f"(x));
    return y;
}
__device__ __forceinline__ float sigfast(float x) {
    return fmaf(tanhfast(0.5f*x), 0.5f, 0.5f);
}

__global__ void __launch_bounds__(BLOCK, 1)
cgrnn_persistent(const float* __restrict__ obs,
                 const float* __restrict__ mask,
                 const int*   __restrict__ lengths,
                 const float* __restrict__ avg,
                 const float* __restrict__ vpe,
                 const float* __restrict__ rarW,
                 const float* __restrict__ adjI,
                 const float* __restrict__ W1,
                 const float* __restrict__ b1,
                 const float* __restrict__ W2,
                 const float* __restrict__ b2,
                 const float* __restrict__ Wr, const float* __restrict__ brp,
                 const float* __restrict__ Wu, const float* __restrict__ bup,
                 const float* __restrict__ Wc, const float* __restrict__ bcp,
                 float* __restrict__ out)
{
    extern __shared__ char smem_raw[];
    float* sm = (float*)smem_raw;
    float* Wst    = sm + OFF_W;
    float* beff_s = sm + OFF_BEFF;
    float* scrU   = sm + U_OFF;
    float* hsB    = sm + HS_OFF;
    float* zcs    = sm + ZCS_OFF;
    int*   listB  = (int*)(sm + LB_OFF);
    int*   listU  = (int*)(sm + LB_OFF + 32);
    int*   lenS   = (int*)(sm + LB_OFF + 64);
    int*   pnB    = (int*)(sm + LB_OFF + 96);
    float* cxsB   = sm + CX_OFF;
    const int tid  = threadIdx.x;
    const int bid  = blockIdx.x;
    const int warp = tid >> 5;
    const int lane = tid & 31;
    const int n_node = bid;

    float* combs = scrU + 0;       // Phase B staging [32][132]
    float* usB   = scrU + 4224;    // [32][64]

    // ========== P1: hypernetwork vv ==========
    {
        float* part = scrU;
        float* hid  = scrU + 1024;
        float* vvs  = scrU + 1152;
        int q = tid >> 7, col = tid & 127;
        const float* vrow = vpe + n_node*768;
        float acc = 0.0f;
        int k0 = q * 96;
        #pragma unroll 4
        for (int k = k0; k < k0 + 96; k++)
            acc = fmaf(vrow[k], W1[k*128 + col], acc);
        part[tid] = acc;
        __syncthreads();
        if (tid < 128) {
            float h = b1[tid];
            #pragma unroll
            for (int qq = 0; qq < 8; qq++) h += part[qq*128 + tid];
            hid[tid] = fmaxf(h, 0.0f);
        }
        __syncthreads();
        if (tid < 5) {
            float a = b2[tid];
            for (int d = 0; d < 128; d++)
                a = fmaf(hid[d], W2[d*5 + tid], a);
            vvs[tid] = a;
        }
        __syncthreads();

        float v0 = vvs[0], v1 = vvs[1], v2 = vvs[2], v3 = vvs[3], v4 = vvs[4];
        __syncthreads();
        for (int idx = tid; idx < 3*KD132; idx += BLOCK) {
            int g  = idx / KD132;
            int kd = idx - g*KD132;
            int kk = kd >> 6;
            int d  = kd & 63;
            float a = 0.0f;
            if (kk < 65 || kk >= 68) {
                int ko = (kk < 65) ? kk : (kk - 3);
                const float* src = (g == 0) ? Wr : (g == 1) ? Wu : Wc;
                int off = ko*64 + d;
                a = v0 * src[off];
                a = fmaf(v1, src[KD + off], a);
                a = fmaf(v2, src[2*KD + off], a);
                a = fmaf(v3, src[3*KD + off], a);
                a = fmaf(v4, src[4*KD + off], a);
            }
            Wst[idx] = a;
        }
        for (int idx = tid; idx < 3*D_; idx += BLOCK) {
            int g = idx >> 6;
            int d = idx & 63;
            const float* src = (g == 0) ? brp : (g == 1) ? bup : bcp;
            float a = v0 * src[d];
            a = fmaf(v1, src[D_ + d], a);
            a = fmaf(v2, src[2*D_ + d], a);
            a = fmaf(v3, src[3*D_ + d], a);
            a = fmaf(v4, src[4*D_ + d], a);
            beff_s[idx] = a;
        }
    }

    // ===== P2b: inv_tot, P/Q, zero h, persistent init =====
    {
        for (int k = tid; k < 32; k += BLOCK) {
            int idx = bid*32 + k;
            int b = idx >> 7;
            int n = idx & 127;
            float s = 0.0f;
            for (int t = 0; t < T_; t++) s += mask[(b*T_ + t)*N_ + n];
            g_invtot[idx] = 1.0f / (s + 1.0f);
        }
        for (int idx = bid*BLOCK + tid; idx < N_*N_; idx += GRID*BLOCK) {
            int j = idx >> 7, i = idx & 127;
            float a = adjI[i*N_ + j];
            g_P[idx] = a;
            g_Q[idx] = a * rarW[i*N_ + j];
        }
        for (int idx = bid*BLOCK + tid; idx < HSZ; idx += GRID*BLOCK)
            g_hbuf[idx] = 0.0f;
        for (int idx = tid; idx < B_*D_; idx += BLOCK) hsB[idx] = 0.0f;
        for (int idx = tid; idx < B_*16; idx += BLOCK) {
            int b = idx >> 4, qq = idx & 15;
            *(float4*)(zcs + b*KR + qq*4) =
                *(const float4*)(obs + (size_t)((b*T_)*N_ + n_node)*D_ + qq*4);
        }
        if (tid < 32) {
            float* zr = zcs + tid*KR;
            zr[65] = 0.0f; zr[66] = 0.0f; zr[67] = 0.0f;
            lenS[tid] = lengths[tid];
        }
    }
    grid_barrier();
    if (tid < 32) {
        zcs[tid*KR + 64] =
            0.5f * tanhfast(avg[(tid*T_)*N_ + n_node] * g_invtot[tid*N_ + n_node]);
    }
    __syncthreads();

    // Phase A scratch aliases
    float* feat = scrU + 0;              // [128][132]
    float* wT   = scrU + 16896;          // [128][32]
    float* rsv  = scrU + 20992;          // [128]
    int*   list = (int*)(scrU + 21120);  // [128]
    int*   cnt  = (int*)(scrU + 21248);  // [8]

    const int dgrp = lane >> 1;
    const int ks   = lane & 1;
    const int d0   = dgrp * 4;

    // ========== time loop ==========
    for (int t = 0; t < T_; t++) {
        const float* hprev = g_hbuf + (t & 1) * HSZ;
        float*       hnext = g_hbuf + ((t + 1) & 1) * HSZ;
        const int b = bid >> 2;
        const int q = bid & 3;

        // ---- A-setup (h-independent) BEFORE barrier 1 ----
        if (tid < 128) {
            float m = mask[(b*T_ + t)*N_ + tid];
            rsv[tid] = 0.5f * tanhfast(avg[(b*T_ + t)*N_ + tid] * g_invtot[b*N_ + tid]);
            bool ob = (m != 0.0f);
            unsigned msk = __ballot_sync(0xffffffffu, ob);
            if (lane == 0) { cnt[warp] = __popc(msk); ((unsigned*)cnt)[4 + warp] = msk; }
        }
        if (tid >= 128 && tid < 160) {
            int bb = tid - 128;
            float m = mask[(bb*T_ + t)*N_ + n_node];
            bool ob = (m != 0.0f);
            unsigned msk = __ballot_sync(0xffffffffu, ob);
            unsigned msku = ~msk;
            if (ob) listB[__popc(msk & ((1u << bb) - 1u))] = bb;
            else    listU[__popc(msku & ((1u << bb) - 1u))] = bb;
            if (bb == 0) *pnB = __popc(msk);
        }
        __syncthreads();
        const int nobs = cnt[0] + cnt[1] + cnt[2] + cnt[3];
        const int nB   = *pnB;
        const int BG4  = (nB + 3) >> 2;
        if (tid < 128) {
            unsigned msk = ((unsigned*)cnt)[4 + warp];
            if ((msk >> lane) & 1u) {
                int off = __popc(msk & ((1u << lane) - 1u));
                for (int ww = 0; ww < warp; ww++) off += cnt[ww];
                list[off] = tid;
            }
        }
        __syncthreads();

        const int lo  = (nobs * q) >> 2;
        const int hi  = (nobs * (q + 1)) >> 2;
        const int myn = hi - lo;

        if (warp < 24) {
            // feat x|rs|pads staging (warps 0..23)
            for (int idx = tid; idx < nobs*16; idx += 768) {
                int jc = idx >> 4, qq = idx & 15;
                int j = list[jc];
                *(float4*)(feat + jc*KR + qq*4) =
                    *(const float4*)(obs + (size_t)((b*T_ + t)*N_ + j)*D_ + qq*4);
            }
            if (tid < nobs) {
                float* fr = feat + tid*KR;
                fr[64] = rsv[list[tid]];
                fr[65] = 0.0f; fr[66] = 0.0f; fr[67] = 0.0f;
            }
            // wT staging
            {
                int ic  = lane;
                int i   = (ic < myn) ? list[lo + ic] : 0;
                float rsi = rsv[i];
                bool valid = (ic < myn);
                for (int jc = warp; jc < nobs; jc += 24) {
                    int j = list[jc];
                    float wv = 0.0f;
                    if (valid) {
                        if (j == i) wv = 1.0f;
                        else wv = g_P[j*N_ + i] - g_Q[j*N_ + i] * fabsf(rsi - rsv[j]);
                    }
                    wT[jc*32 + ic] = wv;
                }
            }
        } else {
            // ---- candx (h-independent), warps 24..31 ----
            int bgrp = warp - 24;
            if (bgrp < BG4 && nB > 0) {
                int bb[4];
                #pragma unroll
                for (int i = 0; i < 4; i++) bb[i] = listB[min(bgrp*4 + i, nB - 1)];
                const float* Wg = Wst + 2*KD132;
                int k2lo = ks ? 17 : 0, k2hi = ks ? 34 : 17;
                float acc[4][4];
                #pragma unroll
                for (int i = 0; i < 4; i++)
                    #pragma unroll
                    for (int j = 0; j < 4; j++) acc[i][j] = 0.0f;
                const float* c0p = zcs + bb[0]*KR;
                const float* c1p = zcs + bb[1]*KR;
                const float* c2p = zcs + bb[2]*KR;
                const float* c3p = zcs + bb[3]*KR;
                #pragma unroll 2
                for (int k2 = k2lo; k2 < k2hi; k2++) {
                    float2 c0 = *(const float2*)(c0p + 2*k2);
                    float2 c1 = *(const float2*)(c1p + 2*k2);
                    float2 c2 = *(const float2*)(c2p + 2*k2);
                    float2 c3 = *(const float2*)(c3p + 2*k2);
                    float4 wA = *(const float4*)(Wg + (2*k2)*64 + d0);
                    float4 wB = *(const float4*)(Wg + (2*k2 + 1)*64 + d0);
                    acc[0][0] = fmaf(c0.x, wA.x, acc[0][0]); acc[0][0] = fmaf(c0.y, wB.x, acc[0][0]);
                    acc[0][1] = fmaf(c0.x, wA.y, acc[0][1]); acc[0][1] = fmaf(c0.y, wB.y, acc[0][1]);
                    acc[0][2] = fmaf(c0.x, wA.z, acc[0][2]); acc[0][2] = fmaf(c0.y, wB.z, acc[0][2]);
                    acc[0][3] = fmaf(c0.x, wA.w, acc[0][3]); acc[0][3] = fmaf(c0.y, wB.w, acc[0][3]);
                    acc[1][0] = fmaf(c1.x, wA.x, acc[1][0]); acc[1][0] = fmaf(c1.y, wB.x, acc[1][0]);
                    acc[1][1] = fmaf(c1.x, wA.y, acc[1][1]); acc[1][1] = fmaf(c1.y, wB.y, acc[1][1]);
                    acc[1][2] = fmaf(c1.x, wA.z, acc[1][2]); acc[1][2] = fmaf(c1.y, wB.z, acc[1][2]);
                    acc[1][3] = fmaf(c1.x, wA.w, acc[1][3]); acc[1][3] = fmaf(c1.y, wB.w, acc[1][3]);
                    acc[2][0] = fmaf(c2.x, wA.x, acc[2][0]); acc[2][0] = fmaf(c2.y, wB.x, acc[2][0]);
                    acc[2][1] = fmaf(c2.x, wA.y, acc[2][1]); acc[2][1] = fmaf(c2.y, wB.y, acc[2][1]);
                    acc[2][2] = fmaf(c2.x, wA.z, acc[2][2]); acc[2][2] = fmaf(c2.y, wB.z, acc[2][2]);
                    acc[2][3] = fmaf(c2.x, wA.w, acc[2][3]); acc[2][3] = fmaf(c2.y, wB.w, acc[2][3]);
                    acc[3][0] = fmaf(c3.x, wA.x, acc[3][0]); acc[3][0] = fmaf(c3.y, wB.x, acc[3][0]);
                    acc[3][1] = fmaf(c3.x, wA.y, acc[3][1]); acc[3][1] = fmaf(c3.y, wB.y, acc[3][1]);
                    acc[3][2] = fmaf(c3.x, wA.z, acc[3][2]); acc[3][2] = fmaf(c3.y, wB.z, acc[3][2]);
                    acc[3][3] = fmaf(c3.x, wA.w, acc[3][3]); acc[3][3] = fmaf(c3.y, wB.w, acc[3][3]);
                }
                #pragma unroll
                for (int i = 0; i < 4; i++)
                    #pragma unroll
                    for (int j = 0; j < 4; j++)
                        acc[i][j] += __shfl_xor_sync(0xffffffffu, acc[i][j], 1);
                if (ks == 0) {
                    float4 bias = *(const float4*)(beff_s + 2*64 + d0);
                    #pragma unroll
                    for (int i = 0; i < 4; i++) {
                        *(float4*)(cxsB + bb[i]*64 + d0) =
                            make_float4(acc[i][0] + bias.x, acc[i][1] + bias.y,
                                        acc[i][2] + bias.z, acc[i][3] + bias.w);
                    }
                }
            }
        }

        grid_barrier();   // h(t) ready everywhere

        // ---- feat-h staging + A-GEMM (2r1c) ----
        for (int idx = tid; idx < nobs*16; idx += BLOCK) {
            int jc = idx >> 4, qq = idx & 15;
            int j = list[jc];
            *(float4*)(feat + jc*KR + 68 + qq*4) =
                *(const float4*)(hprev + (size_t)(b*N_ + j)*D_ + qq*4);
        }
        __syncthreads();

        const int RG2 = (myn + 1) >> 1;
        for (int tt = tid; tt < RG2*132; tt += BLOCK) {
            int rg = tt / 132;
            int cc = tt - rg*132;
            const float* wp = wT + rg*2;
            const float* fp = feat + cc;
            float ax = 0.f, bx = 0.f;
            #pragma unroll 4
            for (int jc = 0; jc < nobs; jc++) {
                float2 w2 = *(const float2*)(wp + jc*32);
                float  fv = fp[jc*KR];
                ax = fmaf(w2.x, fv, ax);
                bx = fmaf(w2.y, fv, bx);
            }
            int ic0 = rg*2;
            {
                int i = list[lo + ic0];
                g_comb[(size_t)(b*N_ + i)*KR + cc] = ax;
            }
            if (ic0 + 1 < myn) {
                int i1 = list[lo + ic0 + 1];
                g_comb[(size_t)(b*N_ + i1)*KR + cc] = bx;
            }
        }

        grid_barrier();   // g_comb ready

        // ---------------- Phase B ----------------
        {
            const int n = n_node;

            for (int idx = tid; idx < nB*33; idx += BLOCK) {
                int bc = idx / 33;
                int qq = idx - bc*33;
                int bb = listB[bc];
                *(float4*)(combs + bb*KR + qq*4) =
                    *(const float4*)(g_comb + (size_t)(bb*N_ + n)*KR + qq*4);
            }
            __syncthreads();

            // ---- pass1: warps 0..15 r/u; warps 16..31 prefetch t+1 ----
            if (warp < 16) {
                if (warp < 2*BG4 && nB > 0) {
                    int g    = warp & 1;
                    int bgrp = warp >> 1;
                    int bb[4];
                    #pragma unroll
                    for (int i = 0; i < 4; i++) bb[i] = listB[min(bgrp*4 + i, nB - 1)];
                    const float* Wg = Wst + g*KD132;
                    int k2lo = ks ? 33 : 0, k2hi = ks ? 66 : 33;
                    float acc[4][4];
                    #pragma unroll
                    for (int i = 0; i < 4; i++)
                        #pragma unroll
                        for (int j = 0; j < 4; j++) acc[i][j] = 0.0f;
                    const float* c0p = combs + bb[0]*KR;
                    const float* c1p = combs + bb[1]*KR;
                    const float* c2p = combs + bb[2]*KR;
                    const float* c3p = combs + bb[3]*KR;
                    #pragma unroll 2
                    for (int k2 = k2lo; k2 < k2hi; k2++) {
                        float2 c0 = *(const float2*)(c0p + 2*k2);
                        float2 c1 = *(const float2*)(c1p + 2*k2);
                        float2 c2 = *(const float2*)(c2p + 2*k2);
                        float2 c3 = *(const float2*)(c3p + 2*k2);
                        float4 wA = *(const float4*)(Wg + (2*k2)*64 + d0);
                        float4 wB = *(const float4*)(Wg + (2*k2 + 1)*64 + d0);
                        acc[0][0] = fmaf(c0.x, wA.x, acc[0][0]); acc[0][0] = fmaf(c0.y, wB.x, acc[0][0]);
                        acc[0][1] = fmaf(c0.x, wA.y, acc[0][1]); acc[0][1] = fmaf(c0.y, wB.y, acc[0][1]);
                        acc[0][2] = fmaf(c0.x, wA.z, acc[0][2]); acc[0][2] = fmaf(c0.y, wB.z, acc[0][2]);
                        acc[0][3] = fmaf(c0.x, wA.w, acc[0][3]); acc[0][3] = fmaf(c0.y, wB.w, acc[0][3]);
                        acc[1][0] = fmaf(c1.x, wA.x, acc[1][0]); acc[1][0] = fmaf(c1.y, wB.x, acc[1][0]);
                        acc[1][1] = fmaf(c1.x, wA.y, acc[1][1]); acc[1][1] = fmaf(c1.y, wB.y, acc[1][1]);
                        acc[1][2] = fmaf(c1.x, wA.z, acc[1][2]); acc[1][2] = fmaf(c1.y, wB.z, acc[1][2]);
                        acc[1][3] = fmaf(c1.x, wA.w, acc[1][3]); acc[1][3] = fmaf(c1.y, wB.w, acc[1][3]);
                        acc[2][0] = fmaf(c2.x, wA.x, acc[2][0]); acc[2][0] = fmaf(c2.y, wB.x, acc[2][0]);
                        acc[2][1] = fmaf(c2.x, wA.y, acc[2][1]); acc[2][1] = fmaf(c2.y, wB.y, acc[2][1]);
                        acc[2][2] = fmaf(c2.x, wA.z, acc[2][2]); acc[2][2] = fmaf(c2.y, wB.z, acc[2][2]);
                        acc[2][3] = fmaf(c2.x, wA.w, acc[2][3]); acc[2][3] = fmaf(c2.y, wB.w, acc[2][3]);
                        acc[3][0] = fmaf(c3.x, wA.x, acc[3][0]); acc[3][0] = fmaf(c3.y, wB.x, acc[3][0]);
                        acc[3][1] = fmaf(c3.x, wA.y, acc[3][1]); acc[3][1] = fmaf(c3.y, wB.y, acc[3][1]);
                        acc[3][2] = fmaf(c3.x, wA.z, acc[3][2]); acc[3][2] = fmaf(c3.y, wB.z, acc[3][2]);
                        acc[3][3] = fmaf(c3.x, wA.w, acc[3][3]); acc[3][3] = fmaf(c3.y, wB.w, acc[3][3]);
                    }
                    #pragma unroll
                    for (int i = 0; i < 4; i++)
                        #pragma unroll
                        for (int j = 0; j < 4; j++)
                            acc[i][j] += __shfl_xor_sync(0xffffffffu, acc[i][j], 1);

                    if (ks == 0) {
                        float4 bias = *(const float4*)(beff_s + g*64 + d0);
                        #pragma unroll
                        for (int i = 0; i < 4; i++) {
                            int bb2 = bb[i];
                            float4 v = make_float4(acc[i][0] + bias.x, acc[i][1] + bias.y,
                                                   acc[i][2] + bias.z, acc[i][3] + bias.w);
                            if (g == 0) {
                                float4 h = *(const float4*)(hsB + bb2*64 + d0);
                                *(float4*)(zcs + bb2*KR + 68 + d0) =
                                    make_float4(sigfast(v.x)*h.x, sigfast(v.y)*h.y,
                                                sigfast(v.z)*h.z, sigfast(v.w)*h.w);
                            } else {
                                *(float4*)(usB + bb2*64 + d0) =
                                    make_float4(sigfast(v.x), sigfast(v.y),
                                                sigfast(v.z), sigfast(v.w));
                            }
                        }
                    }
                }
            } else {
                // prefetch next step zcs x + rs (writes cols 0..64 only)
                if (t + 1 < T_) {
                    for (int idx = tid - 512; idx < B_*16; idx += 512) {
                        int bb2 = idx >> 4, qq = idx & 15;
                        *(float4*)(zcs + bb2*KR + qq*4) =
                            *(const float4*)(obs + (size_t)((bb2*T_ + t + 1)*N_ + n)*D_ + qq*4);
                    }
                    int l2 = tid - 512;
                    if (l2 < 32) {
                        zcs[l2*KR + 64] =
                            0.5f * tanhfast(avg[(l2*T_ + t + 1)*N_ + n] * g_invtot[l2*N_ + n]);
                    }
                }
            }
            __syncthreads();

            // ---- pass2: candh warps [0,BG4); carry on the rest ----
            if (warp < BG4 && nB > 0) {
                int bgrp = warp;
                int bb[4];
                #pragma unroll
                for (int i = 0; i < 4; i++) bb[i] = listB[min(bgrp*4 + i, nB - 1)];
                const float* Wg = Wst + 2*KD132;
                int k2lo = ks ? 50 : 34;
                int k2hi = ks ? 66 : 50;
                float acc[4][4];
                #pragma unroll
                for (int i = 0; i < 4; i++)
                    #pragma unroll
                    for (int j = 0; j < 4; j++) acc[i][j] = 0.0f;
                const float* c0p = zcs + bb[0]*KR;
                const float* c1p = zcs + bb[1]*KR;
                const float* c2p = zcs + bb[2]*KR;
                const float* c3p = zcs + bb[3]*KR;
                #pragma unroll 2
                for (int k2 = k2lo; k2 < k2hi; k2++) {
                    float2 c0 = *(const float2*)(c0p + 2*k2);
                    float2 c1 = *(const float2*)(c1p + 2*k2);
                    float2 c2 = *(const float2*)(c2p + 2*k2);
                    float2 c3 = *(const float2*)(c3p + 2*k2);
                    float4 wA = *(const float4*)(Wg + (2*k2)*64 + d0);
                    float4 wB = *(const float4*)(Wg + (2*k2 + 1)*64 + d0);
                    acc[0][0] = fmaf(c0.x, wA.x, acc[0][0]); acc[0][0] = fmaf(c0.y, wB.x, acc[0][0]);
                    acc[0][1] = fmaf(c0.x, wA.y, acc[0][1]); acc[0][1] = fmaf(c0.y, wB.y, acc[0][1]);
                    acc[0][2] = fmaf(c0.x, wA.z, acc[0][2]); acc[0][2] = fmaf(c0.y, wB.z, acc[0][2]);
                    acc[0][3] = fmaf(c0.x, wA.w, acc[0][3]); acc[0][3] = fmaf(c0.y, wB.w, acc[0][3]);
                    acc[1][0] = fmaf(c1.x, wA.x, acc[1][0]); acc[1][0] = fmaf(c1.y, wB.x, acc[1][0]);
                    acc[1][1] = fmaf(c1.x, wA.y, acc[1][1]); acc[1][1] = fmaf(c1.y, wB.y, acc[1][1]);
                    acc[1][2] = fmaf(c1.x, wA.z, acc[1][2]); acc[1][2] = fmaf(c1.y, wB.z, acc[1][2]);
                    acc[1][3] = fmaf(c1.x, wA.w, acc[1][3]); acc[1][3] = fmaf(c1.y, wB.w, acc[1][3]);
                    acc[2][0] = fmaf(c2.x, wA.x, acc[2][0]); acc[2][0] = fmaf(c2.y, wB.x, acc[2][0]);
                    acc[2][1] = fmaf(c2.x, wA.y, acc[2][1]); acc[2][1] = fmaf(c2.y, wB.y, acc[2][1]);
                    acc[2][2] = fmaf(c2.x, wA.z, acc[2][2]); acc[2][2] = fmaf(c2.y, wB.z, acc[2][2]);
                    acc[2][3] = fmaf(c2.x, wA.w, acc[2][3]); acc[2][3] = fmaf(c2.y, wB.w, acc[2][3]);
                    acc[3][0] = fmaf(c3.x, wA.x, acc[3][0]); acc[3][0] = fmaf(c3.y, wB.x, acc[3][0]);
                    acc[3][1] = fmaf(c3.x, wA.y, acc[3][1]); acc[3][1] = fmaf(c3.y, wB.y, acc[3][1]);
                    acc[3][2] = fmaf(c3.x, wA.z, acc[3][2]); acc[3][2] = fmaf(c3.y, wB.z, acc[3][2]);
                    acc[3][3] = fmaf(c3.x, wA.w, acc[3][3]); acc[3][3] = fmaf(c3.y, wB.w, acc[3][3]);
                }
                #pragma unroll
                for (int i = 0; i < 4; i++)
                    #pragma unroll
                    for (int j = 0; j < 4; j++)
                        acc[i][j] += __shfl_xor_sync(0xffffffffu, acc[i][j], 1);

                if (ks == 0) {
                    #pragma unroll
                    for (int i = 0; i < 4; i++) {
                        int bb2 = bb[i];
                        float4 cx = *(const float4*)(cxsB + bb2*64 + d0);
                        float4 h1 = *(const float4*)(zcs + bb2*KR + 68 + d0);
                        float4 u  = *(const float4*)(usB + bb2*64 + d0);
                        float4 v;
                        v.x = h1.x + u.x*(tanhfast(acc[i][0] + cx.x) - h1.x);
                        v.y = h1.y + u.y*(tanhfast(acc[i][1] + cx.y) - h1.y);
                        v.z = h1.z + u.z*(tanhfast(acc[i][2] + cx.z) - h1.z);
                        v.w = h1.w + u.w*(tanhfast(acc[i][3] + cx.w) - h1.w);
                        *(float4*)(hnext + (size_t)(bb2*N_ + n)*D_ + d0) = v;
                        *(float4*)(hsB + bb2*64 + d0) = v;
                        if (t == lenS[bb2] - 1)
                            *(float4*)(out + (size_t)(bb2*N_ + n)*D_ + d0) = v;
                    }
                }
            } else if (warp >= BG4) {
                int w2 = warp - BG4;
                int nU = B_ - nB;
                int pairs = (nU + 1) >> 1;
                if (w2 < pairs) {
                    int iu = w2 * 2;
                    int dd = lane * 2;
                    #pragma unroll
                    for (int rep = 0; rep < 2; rep++) {
                        if (iu + rep < nU) {
                            int bb2 = listU[iu + rep];
                            float2 v = *(const float2*)(hsB + bb2*64 + dd);
                            *(float2*)(hnext + (size_t)(bb2*N_ + n)*D_ + dd) = v;
                            if (t == lenS[bb2] - 1)
                                *(float2*)(out + (size_t)(bb2*N_ + n)*D_ + dd) = v;
                        }
                    }
                }
            }
        }
        __syncthreads();   // protect scrU + zcs reuse by next iteration
    }
}

extern "C" void kernel_launch(void* const* d_in, const int* in_sizes, int n_in,
                              void* d_out, int out_size) {
    const float* obs     = (const float*)d_in[0];
    const float* mask    = (const float*)d_in[2];
    const int*   lengths = (const int*)d_in[5];
    const float* avg     = (const float*)d_in[6];
    const float* vpe     = (const float*)d_in[7];
    const float* rarW    = (const float*)d_in[8];
    const float* adjI    = (const float*)d_in[9];
    const float* W1      = (const float*)d_in[10];
    const float* b1      = (const float*)d_in[11];
    const float* W2      = (const float*)d_in[12];
    const float* b2      = (const float*)d_in[13];
    const float* Wu      = (const float*)d_in[14];
    const float* bu      = (const float*)d_in[15];
    const float* Wr      = (const float*)d_in[16];
    const float* br      = (const float*)d_in[17];
    const float* Wc      = (const float*)d_in[18];
    const float* bc      = (const float*)d_in[19];
    float* out = (float*)d_out;

    cudaFuncSetAttribute(cgrnn_persistent,
                         cudaFuncAttributeMaxDynamicSharedMemorySize, SMEM_BYTES);
    cgrnn_persistent<<<GRID, BLOCK, SMEM_BYTES>>>(
        obs, mask, lengths, avg, vpe, rarW, adjI,
        W1, b1, W2, b2, Wr, br, Wu, bu, Wc, bc, out);
}

// round 16
// speedup vs baseline: 1.2095x; 1.0479x over previous
#include <cuda_runtime.h>
#include <cuda_bf16.h>
#include <math.h>

#define B_ 32
#define T_ 64
#define N_ 128
#define D_ 64
#define K2 129
#define KD (K2*D_)
#define KR 132              // [x 0..63 | rs 64 | pad 65..67 | h 68..131]
#define KD132 (KR*D_)
#define HSZ (B_*N_*D_)
#define GRID 128
#define BLOCK 1024

// ---- smem layout (floats) ----
#define OFF_W     0                    // 3*KD132 (W[g][k][d], k-major)
#define OFF_BEFF  (3*KD132)            // 192
#define U_OFF     (3*KD132 + 192)      // union scratch
#define U_SIZE    21256
#define HS_OFF    (U_OFF + U_SIZE)     // persistent h [32][64]
#define ZCS_OFF   (HS_OFF + 2048)      // persistent zcs [32][132]
#define LB_OFF    (ZCS_OFF + 4224)     // lists: listB(32) listU(32) lenS(32) pnB(4)
#define CX_OFF    (LB_OFF + 128)       // persistent cxsB [32][64]
#define SMEM_FLOATS (CX_OFF + 2048)
#define SMEM_BYTES  (SMEM_FLOATS*4 + 64)

__device__ float g_invtot[B_*N_];
__device__ float g_hbuf[2*HSZ];
__device__ float g_comb[B_*N_*KR];
__device__ float g_P[N_*N_];
__device__ float g_Q[N_*N_];

__device__ unsigned int g_cnt[8*32];
__device__ unsigned int g_rootc;
__device__ volatile unsigned int g_gen;

__device__ __forceinline__ void grid_barrier() {
    __syncthreads();
    if (threadIdx.x == 0) {
        __threadfence();
        unsigned int gen = g_gen;
        unsigned int grp = blockIdx.x >> 4;
        unsigned int o = atomicAdd(&g_cnt[grp*32], 1u);
        if ((o & 15u) == 15u) {
            unsigned int r = atomicAdd(&g_rootc, 1u);
            if ((r & 7u) == 7u) {
                __threadfence();
                g_gen = gen + 1u;
            }
        }
        while (g_gen == gen) { }
        __threadfence();
    }
    __syncthreads();
}

__device__ __forceinline__ float tanhfast(float x) {
    float y;
    asm("tanh.approx.f32 %0, %1;" : "=f"(y) : "f"(x));
    return y;
}
__device__ __forceinline__ float sigfast(float x) {
    return fmaf(tanhfast(0.5f*x), 0.5f, 0.5f);
}

__global__ void __launch_bounds__(BLOCK, 1)
cgrnn_persistent(const float* __restrict__ obs,
                 const float* __restrict__ mask,
                 const int*   __restrict__ lengths,
                 const float* __restrict__ avg,
                 const float* __restrict__ vpe,
                 const float* __restrict__ rarW,
                 const float* __restrict__ adjI,
                 const float* __restrict__ W1,
                 const float* __restrict__ b1,
                 const float* __restrict__ W2,
                 const float* __restrict__ b2,
                 const float* __restrict__ Wr, const float* __restrict__ brp,
                 const float* __restrict__ Wu, const float* __restrict__ bup,
                 const float* __restrict__ Wc, const float* __restrict__ bcp,
                 float* __restrict__ out)
{
    extern __shared__ char smem_raw[];
    float* sm = (float*)smem_raw;
    float* Wst    = sm + OFF_W;
    float* beff_s = sm + OFF_BEFF;
    float* scrU   = sm + U_OFF;
    float* hsB    = sm + HS_OFF;
    float* zcs    = sm + ZCS_OFF;
    int*   listB  = (int*)(sm + LB_OFF);
    int*   listU  = (int*)(sm + LB_OFF + 32);
    int*   lenS   = (int*)(sm + LB_OFF + 64);
    int*   pnB    = (int*)(sm + LB_OFF + 96);
    float* cxsB   = sm + CX_OFF;
    const int tid  = threadIdx.x;
    const int bid  = blockIdx.x;
    const int warp = tid >> 5;
    const int lane = tid & 31;
    const int n_node = bid;

    float* combs = scrU + 0;       // Phase B staging [32][132]
    float* usB   = scrU + 4224;    // [32][64]

    // ========== P1: hypernetwork vv ==========
    {
        float* part = scrU;
        float* hid  = scrU + 1024;
        float* vvs  = scrU + 1152;
        int q = tid >> 7, col = tid & 127;
        const float* vrow = vpe + n_node*768;
        float acc = 0.0f;
        int k0 = q * 96;
        #pragma unroll 4
        for (int k = k0; k < k0 + 96; k++)
            acc = fmaf(vrow[k], W1[k*128 + col], acc);
        part[tid] = acc;
        __syncthreads();
        if (tid < 128) {
            float h = b1[tid];
            #pragma unroll
            for (int qq = 0; qq < 8; qq++) h += part[qq*128 + tid];
            hid[tid] = fmaxf(h, 0.0f);
        }
        __syncthreads();
        if (tid < 5) {
            float a = b2[tid];
            for (int d = 0; d < 128; d++)
                a = fmaf(hid[d], W2[d*5 + tid], a);
            vvs[tid] = a;
        }
        __syncthreads();

        float v0 = vvs[0], v1 = vvs[1], v2 = vvs[2], v3 = vvs[3], v4 = vvs[4];
        __syncthreads();
        for (int idx = tid; idx < 3*KD132; idx += BLOCK) {
            int g  = idx / KD132;
            int kd = idx - g*KD132;
            int kk = kd >> 6;
            int d  = kd & 63;
            float a = 0.0f;
            if (kk < 65 || kk >= 68) {
                int ko = (kk < 65) ? kk : (kk - 3);
                const float* src = (g == 0) ? Wr : (g == 1) ? Wu : Wc;
                int off = ko*64 + d;
                a = v0 * src[off];
                a = fmaf(v1, src[KD + off], a);
                a = fmaf(v2, src[2*KD + off], a);
                a = fmaf(v3, src[3*KD + off], a);
                a = fmaf(v4, src[4*KD + off], a);
            }
            Wst[idx] = a;
        }
        for (int idx = tid; idx < 3*D_; idx += BLOCK) {
            int g = idx >> 6;
            int d = idx & 63;
            const float* src = (g == 0) ? brp : (g == 1) ? bup : bcp;
            float a = v0 * src[d];
            a = fmaf(v1, src[D_ + d], a);
            a = fmaf(v2, src[2*D_ + d], a);
            a = fmaf(v3, src[3*D_ + d], a);
            a = fmaf(v4, src[4*D_ + d], a);
            beff_s[idx] = a;
        }
    }

    // ===== P2b: inv_tot, P/Q, zero h, persistent init =====
    {
        for (int k = tid; k < 32; k += BLOCK) {
            int idx = bid*32 + k;
            int b = idx >> 7;
            int n = idx & 127;
            float s = 0.0f;
            for (int t = 0; t < T_; t++) s += mask[(b*T_ + t)*N_ + n];
            g_invtot[idx] = 1.0f / (s + 1.0f);
        }
        for (int idx = bid*BLOCK + tid; idx < N_*N_; idx += GRID*BLOCK) {
            int j = idx >> 7, i = idx & 127;
            float a = adjI[i*N_ + j];
            g_P[idx] = a;
            g_Q[idx] = a * rarW[i*N_ + j];
        }
        for (int idx = bid*BLOCK + tid; idx < HSZ; idx += GRID*BLOCK)
            g_hbuf[idx] = 0.0f;
        for (int idx = tid; idx < B_*D_; idx += BLOCK) hsB[idx] = 0.0f;
        for (int idx = tid; idx < B_*16; idx += BLOCK) {
            int b = idx >> 4, qq = idx & 15;
            *(float4*)(zcs + b*KR + qq*4) =
                *(const float4*)(obs + (size_t)((b*T_)*N_ + n_node)*D_ + qq*4);
        }
        if (tid < 32) {
            float* zr = zcs + tid*KR;
            zr[65] = 0.0f; zr[66] = 0.0f; zr[67] = 0.0f;
            lenS[tid] = lengths[tid];
        }
    }
    grid_barrier();
    if (tid < 32) {
        zcs[tid*KR + 64] =
            0.5f * tanhfast(avg[(tid*T_)*N_ + n_node] * g_invtot[tid*N_ + n_node]);
    }
    __syncthreads();

    // Phase A scratch aliases
    float* feat = scrU + 0;              // [128][132]
    float* wT   = scrU + 16896;          // [128][32]
    float* rsv  = scrU + 20992;          // [128]
    int*   list = (int*)(scrU + 21120);  // [128]
    int*   cnt  = (int*)(scrU + 21248);  // [8]

    const int dgrp = lane >> 1;
    const int ks   = lane & 1;
    const int d0   = dgrp * 4;

    // ========== time loop ==========
    for (int t = 0; t < T_; t++) {
        const float* hprev = g_hbuf + (t & 1) * HSZ;
        float*       hnext = g_hbuf + ((t + 1) & 1) * HSZ;
        const int b = bid >> 2;
        const int q = bid & 3;

        // ---- A-setup (h-independent) BEFORE barrier 1 ----
        if (tid < 128) {
            float m = mask[(b*T_ + t)*N_ + tid];
            rsv[tid] = 0.5f * tanhfast(avg[(b*T_ + t)*N_ + tid] * g_invtot[b*N_ + tid]);
            bool ob = (m != 0.0f);
            unsigned msk = __ballot_sync(0xffffffffu, ob);
            if (lane == 0) { cnt[warp] = __popc(msk); ((unsigned*)cnt)[4 + warp] = msk; }
        }
        if (tid >= 128 && tid < 160) {
            int bb = tid - 128;
            float m = mask[(bb*T_ + t)*N_ + n_node];
            bool ob = (m != 0.0f);
            unsigned msk = __ballot_sync(0xffffffffu, ob);
            unsigned msku = ~msk;
            if (ob) listB[__popc(msk & ((1u << bb) - 1u))] = bb;
            else    listU[__popc(msku & ((1u << bb) - 1u))] = bb;
            if (bb == 0) *pnB = __popc(msk);
        }
        __syncthreads();
        const int nobs = cnt[0] + cnt[1] + cnt[2] + cnt[3];
        const int nB   = *pnB;
        const int BG4  = (nB + 3) >> 2;
        if (tid < 128) {
            unsigned msk = ((unsigned*)cnt)[4 + warp];
            if ((msk >> lane) & 1u) {
                int off = __popc(msk & ((1u << lane) - 1u));
                for (int ww = 0; ww < warp; ww++) off += cnt[ww];
                list[off] = tid;
            }
        }
        __syncthreads();

        const int lo  = (nobs * q) >> 2;
        const int hi  = (nobs * (q + 1)) >> 2;
        const int myn = hi - lo;

        if (warp < 24) {
            for (int idx = tid; idx < nobs*16; idx += 768) {
                int jc = idx >> 4, qq = idx & 15;
                int j = list[jc];
                *(float4*)(feat + jc*KR + qq*4) =
                    *(const float4*)(obs + (size_t)((b*T_ + t)*N_ + j)*D_ + qq*4);
            }
            if (tid < nobs) {
                float* fr = feat + tid*KR;
                fr[64] = rsv[list[tid]];
                fr[65] = 0.0f; fr[66] = 0.0f; fr[67] = 0.0f;
            }
            {
                int ic  = lane;
                int i   = (ic < myn) ? list[lo + ic] : 0;
                float rsi = rsv[i];
                bool valid = (ic < myn);
                for (int jc = warp; jc < nobs; jc += 24) {
                    int j = list[jc];
                    float wv = 0.0f;
                    if (valid) {
                        if (j == i) wv = 1.0f;
                        else wv = g_P[j*N_ + i] - g_Q[j*N_ + i] * fabsf(rsi - rsv[j]);
                    }
                    wT[jc*32 + ic] = wv;
                }
            }
        } else {
            // ---- candx (h-independent), warps 24..31 ----
            int bgrp = warp - 24;
            if (bgrp < BG4 && nB > 0) {
                int bb[4];
                #pragma unroll
                for (int i = 0; i < 4; i++) bb[i] = listB[min(bgrp*4 + i, nB - 1)];
                const float* Wg = Wst + 2*KD132;
                int k2lo = ks ? 17 : 0, k2hi = ks ? 34 : 17;
                float acc[4][4];
                #pragma unroll
                for (int i = 0; i < 4; i++)
                    #pragma unroll
                    for (int j = 0; j < 4; j++) acc[i][j] = 0.0f;
                const float* c0p = zcs + bb[0]*KR;
                const float* c1p = zcs + bb[1]*KR;
                const float* c2p = zcs + bb[2]*KR;
                const float* c3p = zcs + bb[3]*KR;
                #pragma unroll 2
                for (int k2 = k2lo; k2 < k2hi; k2++) {
                    float2 c0 = *(const float2*)(c0p + 2*k2);
                    float2 c1 = *(const float2*)(c1p + 2*k2);
                    float2 c2 = *(const float2*)(c2p + 2*k2);
                    float2 c3 = *(const float2*)(c3p + 2*k2);
                    float4 wA = *(const float4*)(Wg + (2*k2)*64 + d0);
                    float4 wB = *(const float4*)(Wg + (2*k2 + 1)*64 + d0);
                    acc[0][0] = fmaf(c0.x, wA.x, acc[0][0]); acc[0][0] = fmaf(c0.y, wB.x, acc[0][0]);
                    acc[0][1] = fmaf(c0.x, wA.y, acc[0][1]); acc[0][1] = fmaf(c0.y, wB.y, acc[0][1]);
                    acc[0][2] = fmaf(c0.x, wA.z, acc[0][2]); acc[0][2] = fmaf(c0.y, wB.z, acc[0][2]);
                    acc[0][3] = fmaf(c0.x, wA.w, acc[0][3]); acc[0][3] = fmaf(c0.y, wB.w, acc[0][3]);
                    acc[1][0] = fmaf(c1.x, wA.x, acc[1][0]); acc[1][0] = fmaf(c1.y, wB.x, acc[1][0]);
                    acc[1][1] = fmaf(c1.x, wA.y, acc[1][1]); acc[1][1] = fmaf(c1.y, wB.y, acc[1][1]);
                    acc[1][2] = fmaf(c1.x, wA.z, acc[1][2]); acc[1][2] = fmaf(c1.y, wB.z, acc[1][2]);
                    acc[1][3] = fmaf(c1.x, wA.w, acc[1][3]); acc[1][3] = fmaf(c1.y, wB.w, acc[1][3]);
                    acc[2][0] = fmaf(c2.x, wA.x, acc[2][0]); acc[2][0] = fmaf(c2.y, wB.x, acc[2][0]);
                    acc[2][1] = fmaf(c2.x, wA.y, acc[2][1]); acc[2][1] = fmaf(c2.y, wB.y, acc[2][1]);
                    acc[2][2] = fmaf(c2.x, wA.z, acc[2][2]); acc[2][2] = fmaf(c2.y, wB.z, acc[2][2]);
                    acc[2][3] = fmaf(c2.x, wA.w, acc[2][3]); acc[2][3] = fmaf(c2.y, wB.w, acc[2][3]);
                    acc[3][0] = fmaf(c3.x, wA.x, acc[3][0]); acc[3][0] = fmaf(c3.y, wB.x, acc[3][0]);
                    acc[3][1] = fmaf(c3.x, wA.y, acc[3][1]); acc[3][1] = fmaf(c3.y, wB.y, acc[3][1]);
                    acc[3][2] = fmaf(c3.x, wA.z, acc[3][2]); acc[3][2] = fmaf(c3.y, wB.z, acc[3][2]);
                    acc[3][3] = fmaf(c3.x, wA.w, acc[3][3]); acc[3][3] = fmaf(c3.y, wB.w, acc[3][3]);
                }
                #pragma unroll
                for (int i = 0; i < 4; i++)
                    #pragma unroll
                    for (int j = 0; j < 4; j++)
                        acc[i][j] += __shfl_xor_sync(0xffffffffu, acc[i][j], 1);
                if (ks == 0) {
                    float4 bias = *(const float4*)(beff_s + 2*64 + d0);
                    #pragma unroll
                    for (int i = 0; i < 4; i++) {
                        *(float4*)(cxsB + bb[i]*64 + d0) =
                            make_float4(acc[i][0] + bias.x, acc[i][1] + bias.y,
                                        acc[i][2] + bias.z, acc[i][3] + bias.w);
                    }
                }
            }
        }

        grid_barrier();   // h(t) ready everywhere

        // ---- feat-h staging + A-GEMM (4 rows x 1 col) ----
        for (int idx = tid; idx < nobs*16; idx += BLOCK) {
            int jc = idx >> 4, qq = idx & 15;
            int j = list[jc];
            *(float4*)(feat + jc*KR + 68 + qq*4) =
                *(const float4*)(hprev + (size_t)(b*N_ + j)*D_ + qq*4);
        }
        __syncthreads();

        const int RG4 = (myn + 3) >> 2;
        for (int tt = tid; tt < RG4*132; tt += BLOCK) {
            int rg = tt / 132;
            int cc = tt - rg*132;
            const float* wp = wT + rg*4;
            const float* fp = feat + cc;
            float4 a = make_float4(0.f, 0.f, 0.f, 0.f);
            #pragma unroll 4
            for (int jc = 0; jc < nobs; jc++) {
                float4 w4 = *(const float4*)(wp + jc*32);
                float  fv = fp[jc*KR];
                a.x = fmaf(w4.x, fv, a.x);
                a.y = fmaf(w4.y, fv, a.y);
                a.z = fmaf(w4.z, fv, a.z);
                a.w = fmaf(w4.w, fv, a.w);
            }
            int ic0 = rg*4;
            float av[4] = {a.x, a.y, a.z, a.w};
            #pragma unroll
            for (int r = 0; r < 4; r++) {
                if (ic0 + r < myn) {
                    int i = list[lo + ic0 + r];
                    g_comb[(size_t)(b*N_ + i)*KR + cc] = av[r];
                }
            }
        }

        grid_barrier();   // g_comb ready

        // ---------------- Phase B ----------------
        {
            const int n = n_node;

            for (int idx = tid; idx < nB*33; idx += BLOCK) {
                int bc = idx / 33;
                int qq = idx - bc*33;
                int bb = listB[bc];
                *(float4*)(combs + bb*KR + qq*4) =
                    *(const float4*)(g_comb + (size_t)(bb*N_ + n)*KR + qq*4);
            }
            __syncthreads();

            // ---- pass1: warps 0..15 r/u; warps 16..31 prefetch t+1 ----
            if (warp < 16) {
                if (warp < 2*BG4 && nB > 0) {
                    int g    = warp & 1;
                    int bgrp = warp >> 1;
                    int bb[4];
                    #pragma unroll
                    for (int i = 0; i < 4; i++) bb[i] = listB[min(bgrp*4 + i, nB - 1)];
                    const float* Wg = Wst + g*KD132;
                    int k2lo = ks ? 33 : 0, k2hi = ks ? 66 : 33;
                    float acc[4][4];
                    #pragma unroll
                    for (int i = 0; i < 4; i++)
                        #pragma unroll
                        for (int j = 0; j < 4; j++) acc[i][j] = 0.0f;
                    const float* c0p = combs + bb[0]*KR;
                    const float* c1p = combs + bb[1]*KR;
                    const float* c2p = combs + bb[2]*KR;
                    const float* c3p = combs + bb[3]*KR;
                    #pragma unroll 2
                    for (int k2 = k2lo; k2 < k2hi; k2++) {
                        float2 c0 = *(const float2*)(c0p + 2*k2);
                        float2 c1 = *(const float2*)(c1p + 2*k2);
                        float2 c2 = *(const float2*)(c2p + 2*k2);
                        float2 c3 = *(const float2*)(c3p + 2*k2);
                        float4 wA = *(const float4*)(Wg + (2*k2)*64 + d0);
                        float4 wB = *(const float4*)(Wg + (2*k2 + 1)*64 + d0);
                        acc[0][0] = fmaf(c0.x, wA.x, acc[0][0]); acc[0][0] = fmaf(c0.y, wB.x, acc[0][0]);
                        acc[0][1] = fmaf(c0.x, wA.y, acc[0][1]); acc[0][1] = fmaf(c0.y, wB.y, acc[0][1]);
                        acc[0][2] = fmaf(c0.x, wA.z, acc[0][2]); acc[0][2] = fmaf(c0.y, wB.z, acc[0][2]);
                        acc[0][3] = fmaf(c0.x, wA.w, acc[0][3]); acc[0][3] = fmaf(c0.y, wB.w, acc[0][3]);
                        acc[1][0] = fmaf(c1.x, wA.x, acc[1][0]); acc[1][0] = fmaf(c1.y, wB.x, acc[1][0]);
                        acc[1][1] = fmaf(c1.x, wA.y, acc[1][1]); acc[1][1] = fmaf(c1.y, wB.y, acc[1][1]);
                        acc[1][2] = fmaf(c1.x, wA.z, acc[1][2]); acc[1][2] = fmaf(c1.y, wB.z, acc[1][2]);
                        acc[1][3] = fmaf(c1.x, wA.w, acc[1][3]); acc[1][3] = fmaf(c1.y, wB.w, acc[1][3]);
                        acc[2][0] = fmaf(c2.x, wA.x, acc[2][0]); acc[2][0] = fmaf(c2.y, wB.x, acc[2][0]);
                        acc[2][1] = fmaf(c2.x, wA.y, acc[2][1]); acc[2][1] = fmaf(c2.y, wB.y, acc[2][1]);
                        acc[2][2] = fmaf(c2.x, wA.z, acc[2][2]); acc[2][2] = fmaf(c2.y, wB.z, acc[2][2]);
                        acc[2][3] = fmaf(c2.x, wA.w, acc[2][3]); acc[2][3] = fmaf(c2.y, wB.w, acc[2][3]);
                        acc[3][0] = fmaf(c3.x, wA.x, acc[3][0]); acc[3][0] = fmaf(c3.y, wB.x, acc[3][0]);
                        acc[3][1] = fmaf(c3.x, wA.y, acc[3][1]); acc[3][1] = fmaf(c3.y, wB.y, acc[3][1]);
                        acc[3][2] = fmaf(c3.x, wA.z, acc[3][2]); acc[3][2] = fmaf(c3.y, wB.z, acc[3][2]);
                        acc[3][3] = fmaf(c3.x, wA.w, acc[3][3]); acc[3][3] = fmaf(c3.y, wB.w, acc[3][3]);
                    }
                    #pragma unroll
                    for (int i = 0; i < 4; i++)
                        #pragma unroll
                        for (int j = 0; j < 4; j++)
                            acc[i][j] += __shfl_xor_sync(0xffffffffu, acc[i][j], 1);

                    if (ks == 0) {
                        float4 bias = *(const float4*)(beff_s + g*64 + d0);
                        #pragma unroll
                        for (int i = 0; i < 4; i++) {
                            int bb2 = bb[i];
                            float4 v = make_float4(acc[i][0] + bias.x, acc[i][1] + bias.y,
                                                   acc[i][2] + bias.z, acc[i][3] + bias.w);
                            if (g == 0) {
                                float4 h = *(const float4*)(hsB + bb2*64 + d0);
                                *(float4*)(zcs + bb2*KR + 68 + d0) =
                                    make_float4(sigfast(v.x)*h.x, sigfast(v.y)*h.y,
                                                sigfast(v.z)*h.z, sigfast(v.w)*h.w);
                            } else {
                                *(float4*)(usB + bb2*64 + d0) =
                                    make_float4(sigfast(v.x), sigfast(v.y),
                                                sigfast(v.z), sigfast(v.w));
                            }
                        }
                    }
                }
            } else {
                if (t + 1 < T_) {
                    for (int idx = tid - 512; idx < B_*16; idx += 512) {
                        int bb2 = idx >> 4, qq = idx & 15;
                        *(float4*)(zcs + bb2*KR + qq*4) =
                            *(const float4*)(obs + (size_t)((bb2*T_ + t + 1)*N_ + n)*D_ + qq*4);
                    }
                    int l2 = tid - 512;
                    if (l2 < 32) {
                        zcs[l2*KR + 64] =
                            0.5f * tanhfast(avg[(l2*T_ + t + 1)*N_ + n] * g_invtot[l2*N_ + n]);
                    }
                }
            }
            __syncthreads();

            // ---- pass2: candh warps [0,BG4); carry on the rest ----
            if (warp < BG4 && nB > 0) {
                int bgrp = warp;
                int bb[4];
                #pragma unroll
                for (int i = 0; i < 4; i++) bb[i] = listB[min(bgrp*4 + i, nB - 1)];
                const float* Wg = Wst + 2*KD132;
                int k2lo = ks ? 50 : 34;
                int k2hi = ks ? 66 : 50;
                float acc[4][4];
                #pragma unroll
                for (int i = 0; i < 4; i++)
                    #pragma unroll
                    for (int j = 0; j < 4; j++) acc[i][j] = 0.0f;
                const float* c0p = zcs + bb[0]*KR;
                const float* c1p = zcs + bb[1]*KR;
                const float* c2p = zcs + bb[2]*KR;
                const float* c3p = zcs + bb[3]*KR;
                #pragma unroll 2
                for (int k2 = k2lo; k2 < k2hi; k2++) {
                    float2 c0 = *(const float2*)(c0p + 2*k2);
                    float2 c1 = *(const float2*)(c1p + 2*k2);
                    float2 c2 = *(const float2*)(c2p + 2*k2);
                    float2 c3 = *(const float2*)(c3p + 2*k2);
                    float4 wA = *(const float4*)(Wg + (2*k2)*64 + d0);
                    float4 wB = *(const float4*)(Wg + (2*k2 + 1)*64 + d0);
                    acc[0][0] = fmaf(c0.x, wA.x, acc[0][0]); acc[0][0] = fmaf(c0.y, wB.x, acc[0][0]);
                    acc[0][1] = fmaf(c0.x, wA.y, acc[0][1]); acc[0][1] = fmaf(c0.y, wB.y, acc[0][1]);
                    acc[0][2] = fmaf(c0.x, wA.z, acc[0][2]); acc[0][2] = fmaf(c0.y, wB.z, acc[0][2]);
                    acc[0][3] = fmaf(c0.x, wA.w, acc[0][3]); acc[0][3] = fmaf(c0.y, wB.w, acc[0][3]);
                    acc[1][0] = fmaf(c1.x, wA.x, acc[1][0]); acc[1][0] = fmaf(c1.y, wB.x, acc[1][0]);
                    acc[1][1] = fmaf(c1.x, wA.y, acc[1][1]); acc[1][1] = fmaf(c1.y, wB.y, acc[1][1]);
                    acc[1][2] = fmaf(c1.x, wA.z, acc[1][2]); acc[1][2] = fmaf(c1.y, wB.z, acc[1][2]);
                    acc[1][3] = fmaf(c1.x, wA.w, acc[1][3]); acc[1][3] = fmaf(c1.y, wB.w, acc[1][3]);
                    acc[2][0] = fmaf(c2.x, wA.x, acc[2][0]); acc[2][0] = fmaf(c2.y, wB.x, acc[2][0]);
                    acc[2][1] = fmaf(c2.x, wA.y, acc[2][1]); acc[2][1] = fmaf(c2.y, wB.y, acc[2][1]);
                    acc[2][2] = fmaf(c2.x, wA.z, acc[2][2]); acc[2][2] = fmaf(c2.y, wB.z, acc[2][2]);
                    acc[2][3] = fmaf(c2.x, wA.w, acc[2][3]); acc[2][3] = fmaf(c2.y, wB.w, acc[2][3]);
                    acc[3][0] = fmaf(c3.x, wA.x, acc[3][0]); acc[3][0] = fmaf(c3.y, wB.x, acc[3][0]);
                    acc[3][1] = fmaf(c3.x, wA.y, acc[3][1]); acc[3][1] = fmaf(c3.y, wB.y, acc[3][1]);
                    acc[3][2] = fmaf(c3.x, wA.z, acc[3][2]); acc[3][2] = fmaf(c3.y, wB.z, acc[3][2]);
                    acc[3][3] = fmaf(c3.x, wA.w, acc[3][3]); acc[3][3] = fmaf(c3.y, wB.w, acc[3][3]);
                }
                #pragma unroll
                for (int i = 0; i < 4; i++)
                    #pragma unroll
                    for (int j = 0; j < 4; j++)
                        acc[i][j] += __shfl_xor_sync(0xffffffffu, acc[i][j], 1);

                if (ks == 0) {
                    #pragma unroll
                    for (int i = 0; i < 4; i++) {
                        int bb2 = bb[i];
                        float4 cx = *(const float4*)(cxsB + bb2*64 + d0);
                        float4 h1 = *(const float4*)(zcs + bb2*KR + 68 + d0);
                        float4 u  = *(const float4*)(usB + bb2*64 + d0);
                        float4 v;
                        v.x = h1.x + u.x*(tanhfast(acc[i][0] + cx.x) - h1.x);
                        v.y = h1.y + u.y*(tanhfast(acc[i][1] + cx.y) - h1.y);
                        v.z = h1.z + u.z*(tanhfast(acc[i][2] + cx.z) - h1.z);
                        v.w = h1.w + u.w*(tanhfast(acc[i][3] + cx.w) - h1.w);
                        *(float4*)(hnext + (size_t)(bb2*N_ + n)*D_ + d0) = v;
                        *(float4*)(hsB + bb2*64 + d0) = v;
                        if (t == lenS[bb2] - 1)
                            *(float4*)(out + (size_t)(bb2*N_ + n)*D_ + d0) = v;
                    }
                }
            } else if (warp >= BG4) {
                int w2 = warp - BG4;
                int nU = B_ - nB;
                int pairs = (nU + 1) >> 1;
                if (w2 < pairs) {
                    int iu = w2 * 2;
                    int dd = lane * 2;
                    #pragma unroll
                    for (int rep = 0; rep < 2; rep++) {
                        if (iu + rep < nU) {
                            int bb2 = listU[iu + rep];
                            float2 v = *(const float2*)(hsB + bb2*64 + dd);
                            *(float2*)(hnext + (size_t)(bb2*N_ + n)*D_ + dd) = v;
                            if (t == lenS[bb2] - 1)
                                *(float2*)(out + (size_t)(bb2*N_ + n)*D_ + dd) = v;
                        }
                    }
                }
            }
        }
        __syncthreads();
    }
}

extern "C" void kernel_launch(void* const* d_in, const int* in_sizes, int n_in,
                              void* d_out, int out_size) {
    const float* obs     = (const float*)d_in[0];
    const float* mask    = (const float*)d_in[2];
    const int*   lengths = (const int*)d_in[5];
    const float* avg     = (const float*)d_in[6];
    const float* vpe     = (const float*)d_in[7];
    const float* rarW    = (const float*)d_in[8];
    const float* adjI    = (const float*)d_in[9];
    const float* W1      = (const float*)d_in[10];
    const float* b1      = (const float*)d_in[11];
    const float* W2      = (const float*)d_in[12];
    const float* b2      = (const float*)d_in[13];
    const float* Wu      = (const float*)d_in[14];
    const float* bu      = (const float*)d_in[15];
    const float* Wr      = (const float*)d_in[16];
    const float* br      = (const float*)d_in[17];
    const float* Wc      = (const float*)d_in[18];
    const float* bc      = (const float*)d_in[19];
    float* out = (float*)d_out;

    cudaFuncSetAttribute(cgrnn_persistent,
                         cudaFuncAttributeMaxDynamicSharedMemorySize, SMEM_BYTES);
    cgrnn_persistent<<<GRID, BLOCK, SMEM_BYTES>>>(
        obs, mask, lengths, avg, vpe, rarW, adjI,
        W1, b1, W2, b2, Wr, br, Wu, bu, Wc, bc, out);
}

// round 17
// speedup vs baseline: 1.2176x; 1.0067x over previous
#include <cuda_runtime.h>
#include <cuda_bf16.h>
#include <math.h>

#define B_ 32
#define T_ 64
#define N_ 128
#define D_ 64
#define K2 129
#define KD (K2*D_)
#define KR 132              // [x 0..63 | rs 64 | pad 65..67 | h 68..131]
#define KD132 (KR*D_)
#define HSZ (B_*N_*D_)
#define GRID 128
#define BLOCK 1024

// ---- smem layout (floats) ----
#define OFF_W     0                    // 3*KD132 (W[g][k][d], k-major)
#define OFF_BEFF  (3*KD132)            // 192
#define U_OFF     (3*KD132 + 192)      // union scratch
#define U_SIZE    21256
#define HS_OFF    (U_OFF + U_SIZE)     // persistent h [32][64]
#define ZCS_OFF   (HS_OFF + 2048)      // persistent zcs [32][132]
#define LB_OFF    (ZCS_OFF + 4224)     // lists: listB(32) listU(32) lenS(32) pnB(4)
#define CX_OFF    (LB_OFF + 128)       // persistent cxsB [32][64]
#define SMEM_FLOATS (CX_OFF + 2048)
#define SMEM_BYTES  (SMEM_FLOATS*4 + 64)

__device__ float g_invtot[B_*N_];
__device__ float g_hbuf[2*HSZ];
__device__ float g_comb[B_*N_*KR];
__device__ float g_P[N_*N_];
__device__ float g_Q[N_*N_];

__device__ unsigned int g_cnt[8*32];
__device__ unsigned int g_rootc;
__device__ volatile unsigned int g_gen;

__device__ __forceinline__ void grid_barrier() {
    __syncthreads();
    if (threadIdx.x == 0) {
        __threadfence();
        unsigned int gen = g_gen;
        unsigned int grp = blockIdx.x >> 4;
        unsigned int o = atomicAdd(&g_cnt[grp*32], 1u);
        if ((o & 15u) == 15u) {
            unsigned int r = atomicAdd(&g_rootc, 1u);
            if ((r & 7u) == 7u) {
                __threadfence();
                g_gen = gen + 1u;
            }
        }
        while (g_gen == gen) { }
        __threadfence();
    }
    __syncthreads();
}

__device__ __forceinline__ float tanhfast(float x) {
    float y;
    asm("tanh.approx.f32 %0, %1;" : "=f"(y) : "f"(x));
    return y;
}
__device__ __forceinline__ float sigfast(float x) {
    return fmaf(tanhfast(0.5f*x), 0.5f, 0.5f);
}

__global__ void __launch_bounds__(BLOCK, 1)
cgrnn_persistent(const float* __restrict__ obs,
                 const float* __restrict__ mask,
                 const int*   __restrict__ lengths,
                 const float* __restrict__ avg,
                 const float* __restrict__ vpe,
                 const float* __restrict__ rarW,
                 const float* __restrict__ adjI,
                 const float* __restrict__ W1,
                 const float* __restrict__ b1,
                 const float* __restrict__ W2,
                 const float* __restrict__ b2,
                 const float* __restrict__ Wr, const float* __restrict__ brp,
                 const float* __restrict__ Wu, const float* __restrict__ bup,
                 const float* __restrict__ Wc, const float* __restrict__ bcp,
                 float* __restrict__ out)
{
    extern __shared__ char smem_raw[];
    float* sm = (float*)smem_raw;
    float* Wst    = sm + OFF_W;
    float* beff_s = sm + OFF_BEFF;
    float* scrU   = sm + U_OFF;
    float* hsB    = sm + HS_OFF;
    float* zcs    = sm + ZCS_OFF;
    int*   listB  = (int*)(sm + LB_OFF);
    int*   listU  = (int*)(sm + LB_OFF + 32);
    int*   lenS   = (int*)(sm + LB_OFF + 64);
    int*   pnB    = (int*)(sm + LB_OFF + 96);
    float* cxsB   = sm + CX_OFF;
    const int tid  = threadIdx.x;
    const int bid  = blockIdx.x;
    const int warp = tid >> 5;
    const int lane = tid & 31;
    const int n_node = bid;

    float* combs = scrU + 0;       // Phase B staging [32][132]
    float* usB   = scrU + 4224;    // [32][64]

    // ========== P1: hypernetwork vv ==========
    {
        float* part = scrU;
        float* hid  = scrU + 1024;
        float* vvs  = scrU + 1152;
        int q = tid >> 7, col = tid & 127;
        const float* vrow = vpe + n_node*768;
        float acc = 0.0f;
        int k0 = q * 96;
        #pragma unroll 4
        for (int k = k0; k < k0 + 96; k++)
            acc = fmaf(vrow[k], W1[k*128 + col], acc);
        part[tid] = acc;
        __syncthreads();
        if (tid < 128) {
            float h = b1[tid];
            #pragma unroll
            for (int qq = 0; qq < 8; qq++) h += part[qq*128 + tid];
            hid[tid] = fmaxf(h, 0.0f);
        }
        __syncthreads();
        if (tid < 5) {
            float a = b2[tid];
            for (int d = 0; d < 128; d++)
                a = fmaf(hid[d], W2[d*5 + tid], a);
            vvs[tid] = a;
        }
        __syncthreads();

        float v0 = vvs[0], v1 = vvs[1], v2 = vvs[2], v3 = vvs[3], v4 = vvs[4];
        __syncthreads();
        for (int idx = tid; idx < 3*KD132; idx += BLOCK) {
            int g  = idx / KD132;
            int kd = idx - g*KD132;
            int kk = kd >> 6;
            int d  = kd & 63;
            float a = 0.0f;
            if (kk < 65 || kk >= 68) {
                int ko = (kk < 65) ? kk : (kk - 3);
                const float* src = (g == 0) ? Wr : (g == 1) ? Wu : Wc;
                int off = ko*64 + d;
                a = v0 * src[off];
                a = fmaf(v1, src[KD + off], a);
                a = fmaf(v2, src[2*KD + off], a);
                a = fmaf(v3, src[3*KD + off], a);
                a = fmaf(v4, src[4*KD + off], a);
            }
            Wst[idx] = a;
        }
        for (int idx = tid; idx < 3*D_; idx += BLOCK) {
            int g = idx >> 6;
            int d = idx & 63;
            const float* src = (g == 0) ? brp : (g == 1) ? bup : bcp;
            float a = v0 * src[d];
            a = fmaf(v1, src[D_ + d], a);
            a = fmaf(v2, src[2*D_ + d], a);
            a = fmaf(v3, src[3*D_ + d], a);
            a = fmaf(v4, src[4*D_ + d], a);
            beff_s[idx] = a;
        }
    }

    // ===== P2b: inv_tot, P/Q, zero h, persistent init =====
    {
        for (int k = tid; k < 32; k += BLOCK) {
            int idx = bid*32 + k;
            int b = idx >> 7;
            int n = idx & 127;
            float s = 0.0f;
            for (int t = 0; t < T_; t++) s += mask[(b*T_ + t)*N_ + n];
            g_invtot[idx] = 1.0f / (s + 1.0f);
        }
        for (int idx = bid*BLOCK + tid; idx < N_*N_; idx += GRID*BLOCK) {
            int j = idx >> 7, i = idx & 127;
            float a = adjI[i*N_ + j];
            g_P[idx] = a;
            g_Q[idx] = a * rarW[i*N_ + j];
        }
        for (int idx = bid*BLOCK + tid; idx < HSZ; idx += GRID*BLOCK)
            g_hbuf[idx] = 0.0f;
        for (int idx = tid; idx < B_*D_; idx += BLOCK) hsB[idx] = 0.0f;
        for (int idx = tid; idx < B_*16; idx += BLOCK) {
            int b = idx >> 4, qq = idx & 15;
            *(float4*)(zcs + b*KR + qq*4) =
                *(const float4*)(obs + (size_t)((b*T_)*N_ + n_node)*D_ + qq*4);
        }
        if (tid < 32) {
            float* zr = zcs + tid*KR;
            zr[65] = 0.0f; zr[66] = 0.0f; zr[67] = 0.0f;
            lenS[tid] = lengths[tid];
        }
    }
    grid_barrier();
    if (tid < 32) {
        zcs[tid*KR + 64] =
            0.5f * tanhfast(avg[(tid*T_)*N_ + n_node] * g_invtot[tid*N_ + n_node]);
    }
    __syncthreads();

    // Phase A scratch aliases
    float* feat = scrU + 0;              // [128][132]
    float* wT   = scrU + 16896;          // [128][32]
    float* rsv  = scrU + 20992;          // [128]
    int*   list = (int*)(scrU + 21120);  // [128]
    int*   cnt  = (int*)(scrU + 21248);  // [8]

    const int dgrp = lane >> 1;
    const int ks   = lane & 1;
    const int d0   = dgrp * 4;

    // ========== time loop ==========
    for (int t = 0; t < T_; t++) {
        const float* hprev = g_hbuf + (t & 1) * HSZ;
        float*       hnext = g_hbuf + ((t + 1) & 1) * HSZ;
        const int b = bid >> 2;
        const int q = bid & 3;

        // ---- A-setup (h-independent) BEFORE barrier 1 ----
        if (tid < 128) {
            float m = mask[(b*T_ + t)*N_ + tid];
            rsv[tid] = 0.5f * tanhfast(avg[(b*T_ + t)*N_ + tid] * g_invtot[b*N_ + tid]);
            bool ob = (m != 0.0f);
            unsigned msk = __ballot_sync(0xffffffffu, ob);
            if (lane == 0) { cnt[warp] = __popc(msk); ((unsigned*)cnt)[4 + warp] = msk; }
        }
        if (tid >= 128 && tid < 160) {
            int bb = tid - 128;
            float m = mask[(bb*T_ + t)*N_ + n_node];
            bool ob = (m != 0.0f);
            unsigned msk = __ballot_sync(0xffffffffu, ob);
            unsigned msku = ~msk;
            if (ob) listB[__popc(msk & ((1u << bb) - 1u))] = bb;
            else    listU[__popc(msku & ((1u << bb) - 1u))] = bb;
            if (bb == 0) *pnB = __popc(msk);
        }
        __syncthreads();
        const int nobs = cnt[0] + cnt[1] + cnt[2] + cnt[3];
        const int nB   = *pnB;
        const int BG4  = (nB + 3) >> 2;
        if (tid < 128) {
            unsigned msk = ((unsigned*)cnt)[4 + warp];
            if ((msk >> lane) & 1u) {
                int off = __popc(msk & ((1u << lane) - 1u));
                for (int ww = 0; ww < warp; ww++) off += cnt[ww];
                list[off] = tid;
            }
        }
        __syncthreads();

        const int lo  = (nobs * q) >> 2;
        const int hi  = (nobs * (q + 1)) >> 2;
        const int myn = hi - lo;
        const int RG4 = (myn + 3) >> 2;

        if (warp < 24) {
            for (int idx = tid; idx < nobs*16; idx += 768) {
                int jc = idx >> 4, qq = idx & 15;
                int j = list[jc];
                *(float4*)(feat + jc*KR + qq*4) =
                    *(const float4*)(obs + (size_t)((b*T_ + t)*N_ + j)*D_ + qq*4);
            }
            if (tid < nobs) {
                float* fr = feat + tid*KR;
                fr[64] = rsv[list[tid]];
                fr[65] = 0.0f; fr[66] = 0.0f; fr[67] = 0.0f;
            }
            {
                int ic  = lane;
                int i   = (ic < myn) ? list[lo + ic] : 0;
                float rsi = rsv[i];
                bool valid = (ic < myn);
                for (int jc = warp; jc < nobs; jc += 24) {
                    int j = list[jc];
                    float wv = 0.0f;
                    if (valid) {
                        if (j == i) wv = 1.0f;
                        else wv = g_P[j*N_ + i] - g_Q[j*N_ + i] * fabsf(rsi - rsv[j]);
                    }
                    wT[jc*32 + ic] = wv;
                }
            }
        } else {
            // ---- candx (h-independent), warps 24..31 ----
            int bgrp = warp - 24;
            if (bgrp < BG4 && nB > 0) {
                int bb[4];
                #pragma unroll
                for (int i = 0; i < 4; i++) bb[i] = listB[min(bgrp*4 + i, nB - 1)];
                const float* Wg = Wst + 2*KD132;
                int k2lo = ks ? 17 : 0, k2hi = ks ? 34 : 17;
                float acc[4][4];
                #pragma unroll
                for (int i = 0; i < 4; i++)
                    #pragma unroll
                    for (int j = 0; j < 4; j++) acc[i][j] = 0.0f;
                const float* c0p = zcs + bb[0]*KR;
                const float* c1p = zcs + bb[1]*KR;
                const float* c2p = zcs + bb[2]*KR;
                const float* c3p = zcs + bb[3]*KR;
                #pragma unroll 2
                for (int k2 = k2lo; k2 < k2hi; k2++) {
                    float2 c0 = *(const float2*)(c0p + 2*k2);
                    float2 c1 = *(const float2*)(c1p + 2*k2);
                    float2 c2 = *(const float2*)(c2p + 2*k2);
                    float2 c3 = *(const float2*)(c3p + 2*k2);
                    float4 wA = *(const float4*)(Wg + (2*k2)*64 + d0);
                    float4 wB = *(const float4*)(Wg + (2*k2 + 1)*64 + d0);
                    acc[0][0] = fmaf(c0.x, wA.x, acc[0][0]); acc[0][0] = fmaf(c0.y, wB.x, acc[0][0]);
                    acc[0][1] = fmaf(c0.x, wA.y, acc[0][1]); acc[0][1] = fmaf(c0.y, wB.y, acc[0][1]);
                    acc[0][2] = fmaf(c0.x, wA.z, acc[0][2]); acc[0][2] = fmaf(c0.y, wB.z, acc[0][2]);
                    acc[0][3] = fmaf(c0.x, wA.w, acc[0][3]); acc[0][3] = fmaf(c0.y, wB.w, acc[0][3]);
                    acc[1][0] = fmaf(c1.x, wA.x, acc[1][0]); acc[1][0] = fmaf(c1.y, wB.x, acc[1][0]);
                    acc[1][1] = fmaf(c1.x, wA.y, acc[1][1]); acc[1][1] = fmaf(c1.y, wB.y, acc[1][1]);
                    acc[1][2] = fmaf(c1.x, wA.z, acc[1][2]); acc[1][2] = fmaf(c1.y, wB.z, acc[1][2]);
                    acc[1][3] = fmaf(c1.x, wA.w, acc[1][3]); acc[1][3] = fmaf(c1.y, wB.w, acc[1][3]);
                    acc[2][0] = fmaf(c2.x, wA.x, acc[2][0]); acc[2][0] = fmaf(c2.y, wB.x, acc[2][0]);
                    acc[2][1] = fmaf(c2.x, wA.y, acc[2][1]); acc[2][1] = fmaf(c2.y, wB.y, acc[2][1]);
                    acc[2][2] = fmaf(c2.x, wA.z, acc[2][2]); acc[2][2] = fmaf(c2.y, wB.z, acc[2][2]);
                    acc[2][3] = fmaf(c2.x, wA.w, acc[2][3]); acc[2][3] = fmaf(c2.y, wB.w, acc[2][3]);
                    acc[3][0] = fmaf(c3.x, wA.x, acc[3][0]); acc[3][0] = fmaf(c3.y, wB.x, acc[3][0]);
                    acc[3][1] = fmaf(c3.x, wA.y, acc[3][1]); acc[3][1] = fmaf(c3.y, wB.y, acc[3][1]);
                    acc[3][2] = fmaf(c3.x, wA.z, acc[3][2]); acc[3][2] = fmaf(c3.y, wB.z, acc[3][2]);
                    acc[3][3] = fmaf(c3.x, wA.w, acc[3][3]); acc[3][3] = fmaf(c3.y, wB.w, acc[3][3]);
                }
                #pragma unroll
                for (int i = 0; i < 4; i++)
                    #pragma unroll
                    for (int j = 0; j < 4; j++)
                        acc[i][j] += __shfl_xor_sync(0xffffffffu, acc[i][j], 1);
                if (ks == 0) {
                    float4 bias = *(const float4*)(beff_s + 2*64 + d0);
                    #pragma unroll
                    for (int i = 0; i < 4; i++) {
                        *(float4*)(cxsB + bb[i]*64 + d0) =
                            make_float4(acc[i][0] + bias.x, acc[i][1] + bias.y,
                                        acc[i][2] + bias.z, acc[i][3] + bias.w);
                    }
                }
            }
        }
        __syncthreads();

        // ---- A-GEMM x-part (cols 0..67), pre-barrier ----
        for (int tt = tid; tt < RG4*68; tt += BLOCK) {
            int rg = tt / 68;
            int cc = tt - rg*68;
            const float* wp = wT + rg*4;
            const float* fp = feat + cc;
            float4 a = make_float4(0.f, 0.f, 0.f, 0.f);
            #pragma unroll 4
            for (int jc = 0; jc < nobs; jc++) {
                float4 w4 = *(const float4*)(wp + jc*32);
                float  fv = fp[jc*KR];
                a.x = fmaf(w4.x, fv, a.x);
                a.y = fmaf(w4.y, fv, a.y);
                a.z = fmaf(w4.z, fv, a.z);
                a.w = fmaf(w4.w, fv, a.w);
            }
            int ic0 = rg*4;
            float av[4] = {a.x, a.y, a.z, a.w};
            #pragma unroll
            for (int r = 0; r < 4; r++) {
                if (ic0 + r < myn) {
                    int i = list[lo + ic0 + r];
                    g_comb[(size_t)(b*N_ + i)*KR + cc] = av[r];
                }
            }
        }

        grid_barrier();   // h(t) ready everywhere

        // ---- feat-h staging + A-GEMM h-part (cols 68..131) ----
        for (int idx = tid; idx < nobs*16; idx += BLOCK) {
            int jc = idx >> 4, qq = idx & 15;
            int j = list[jc];
            *(float4*)(feat + jc*KR + 68 + qq*4) =
                *(const float4*)(hprev + (size_t)(b*N_ + j)*D_ + qq*4);
        }
        __syncthreads();

        for (int tt = tid; tt < RG4*64; tt += BLOCK) {
            int rg = tt >> 6;
            int cc = 68 + (tt & 63);
            const float* wp = wT + rg*4;
            const float* fp = feat + cc;
            float4 a = make_float4(0.f, 0.f, 0.f, 0.f);
            #pragma unroll 4
            for (int jc = 0; jc < nobs; jc++) {
                float4 w4 = *(const float4*)(wp + jc*32);
                float  fv = fp[jc*KR];
                a.x = fmaf(w4.x, fv, a.x);
                a.y = fmaf(w4.y, fv, a.y);
                a.z = fmaf(w4.z, fv, a.z);
                a.w = fmaf(w4.w, fv, a.w);
            }
            int ic0 = rg*4;
            float av[4] = {a.x, a.y, a.z, a.w};
            #pragma unroll
            for (int r = 0; r < 4; r++) {
                if (ic0 + r < myn) {
                    int i = list[lo + ic0 + r];
                    g_comb[(size_t)(b*N_ + i)*KR + cc] = av[r];
                }
            }
        }

        grid_barrier();   // g_comb ready

        // ---------------- Phase B ----------------
        {
            const int n = n_node;

            for (int idx = tid; idx < nB*33; idx += BLOCK) {
                int bc = idx / 33;
                int qq = idx - bc*33;
                int bb = listB[bc];
                *(float4*)(combs + bb*KR + qq*4) =
                    *(const float4*)(g_comb + (size_t)(bb*N_ + n)*KR + qq*4);
            }
            __syncthreads();

            // ---- pass1: warps 0..15 r/u; warps 16..31 prefetch t+1 ----
            if (warp < 16) {
                if (warp < 2*BG4 && nB > 0) {
                    int g    = warp & 1;
                    int bgrp = warp >> 1;
                    int bb[4];
                    #pragma unroll
                    for (int i = 0; i < 4; i++) bb[i] = listB[min(bgrp*4 + i, nB - 1)];
                    const float* Wg = Wst + g*KD132;
                    int k2lo = ks ? 33 : 0, k2hi = ks ? 66 : 33;
                    float acc[4][4];
                    #pragma unroll
                    for (int i = 0; i < 4; i++)
                        #pragma unroll
                        for (int j = 0; j < 4; j++) acc[i][j] = 0.0f;
                    const float* c0p = combs + bb[0]*KR;
                    const float* c1p = combs + bb[1]*KR;
                    const float* c2p = combs + bb[2]*KR;
                    const float* c3p = combs + bb[3]*KR;
                    #pragma unroll 2
                    for (int k2 = k2lo; k2 < k2hi; k2++) {
                        float2 c0 = *(const float2*)(c0p + 2*k2);
                        float2 c1 = *(const float2*)(c1p + 2*k2);
                        float2 c2 = *(const float2*)(c2p + 2*k2);
                        float2 c3 = *(const float2*)(c3p + 2*k2);
                        float4 wA = *(const float4*)(Wg + (2*k2)*64 + d0);
                        float4 wB = *(const float4*)(Wg + (2*k2 + 1)*64 + d0);
                        acc[0][0] = fmaf(c0.x, wA.x, acc[0][0]); acc[0][0] = fmaf(c0.y, wB.x, acc[0][0]);
                        acc[0][1] = fmaf(c0.x, wA.y, acc[0][1]); acc[0][1] = fmaf(c0.y, wB.y, acc[0][1]);
                        acc[0][2] = fmaf(c0.x, wA.z, acc[0][2]); acc[0][2] = fmaf(c0.y, wB.z, acc[0][2]);
                        acc[0][3] = fmaf(c0.x, wA.w, acc[0][3]); acc[0][3] = fmaf(c0.y, wB.w, acc[0][3]);
                        acc[1][0] = fmaf(c1.x, wA.x, acc[1][0]); acc[1][0] = fmaf(c1.y, wB.x, acc[1][0]);
                        acc[1][1] = fmaf(c1.x, wA.y, acc[1][1]); acc[1][1] = fmaf(c1.y, wB.y, acc[1][1]);
                        acc[1][2] = fmaf(c1.x, wA.z, acc[1][2]); acc[1][2] = fmaf(c1.y, wB.z, acc[1][2]);
                        acc[1][3] = fmaf(c1.x, wA.w, acc[1][3]); acc[1][3] = fmaf(c1.y, wB.w, acc[1][3]);
                        acc[2][0] = fmaf(c2.x, wA.x, acc[2][0]); acc[2][0] = fmaf(c2.y, wB.x, acc[2][0]);
                        acc[2][1] = fmaf(c2.x, wA.y, acc[2][1]); acc[2][1] = fmaf(c2.y, wB.y, acc[2][1]);
                        acc[2][2] = fmaf(c2.x, wA.z, acc[2][2]); acc[2][2] = fmaf(c2.y, wB.z, acc[2][2]);
                        acc[2][3] = fmaf(c2.x, wA.w, acc[2][3]); acc[2][3] = fmaf(c2.y, wB.w, acc[2][3]);
                        acc[3][0] = fmaf(c3.x, wA.x, acc[3][0]); acc[3][0] = fmaf(c3.y, wB.x, acc[3][0]);
                        acc[3][1] = fmaf(c3.x, wA.y, acc[3][1]); acc[3][1] = fmaf(c3.y, wB.y, acc[3][1]);
                        acc[3][2] = fmaf(c3.x, wA.z, acc[3][2]); acc[3][2] = fmaf(c3.y, wB.z, acc[3][2]);
                        acc[3][3] = fmaf(c3.x, wA.w, acc[3][3]); acc[3][3] = fmaf(c3.y, wB.w, acc[3][3]);
                    }
                    #pragma unroll
                    for (int i = 0; i < 4; i++)
                        #pragma unroll
                        for (int j = 0; j < 4; j++)
                            acc[i][j] += __shfl_xor_sync(0xffffffffu, acc[i][j], 1);

                    if (ks == 0) {
                        float4 bias = *(const float4*)(beff_s + g*64 + d0);
                        #pragma unroll
                        for (int i = 0; i < 4; i++) {
                            int bb2 = bb[i];
                            float4 v = make_float4(acc[i][0] + bias.x, acc[i][1] + bias.y,
                                                   acc[i][2] + bias.z, acc[i][3] + bias.w);
                            if (g == 0) {
                                float4 h = *(const float4*)(hsB + bb2*64 + d0);
                                *(float4*)(zcs + bb2*KR + 68 + d0) =
                                    make_float4(sigfast(v.x)*h.x, sigfast(v.y)*h.y,
                                                sigfast(v.z)*h.z, sigfast(v.w)*h.w);
                            } else {
                                *(float4*)(usB + bb2*64 + d0) =
                                    make_float4(sigfast(v.x), sigfast(v.y),
                                                sigfast(v.z), sigfast(v.w));
                            }
                        }
                    }
                }
            } else {
                if (t + 1 < T_) {
                    for (int idx = tid - 512; idx < B_*16; idx += 512) {
                        int bb2 = idx >> 4, qq = idx & 15;
                        *(float4*)(zcs + bb2*KR + qq*4) =
                            *(const float4*)(obs + (size_t)((bb2*T_ + t + 1)*N_ + n)*D_ + qq*4);
                    }
                    int l2 = tid - 512;
                    if (l2 < 32) {
                        zcs[l2*KR + 64] =
                            0.5f * tanhfast(avg[(l2*T_ + t + 1)*N_ + n] * g_invtot[l2*N_ + n]);
                    }
                }
            }
            __syncthreads();

            // ---- pass2: candh warps [0,BG4); carry on the rest ----
            if (warp < BG4 && nB > 0) {
                int bgrp = warp;
                int bb[4];
                #pragma unroll
                for (int i = 0; i < 4; i++) bb[i] = listB[min(bgrp*4 + i, nB - 1)];
                const float* Wg = Wst + 2*KD132;
                int k2lo = ks ? 50 : 34;
                int k2hi = ks ? 66 : 50;
                float acc[4][4];
                #pragma unroll
                for (int i = 0; i < 4; i++)
                    #pragma unroll
                    for (int j = 0; j < 4; j++) acc[i][j] = 0.0f;
                const float* c0p = zcs + bb[0]*KR;
                const float* c1p = zcs + bb[1]*KR;
                const float* c2p = zcs + bb[2]*KR;
                const float* c3p = zcs + bb[3]*KR;
                #pragma unroll 2
                for (int k2 = k2lo; k2 < k2hi; k2++) {
                    float2 c0 = *(const float2*)(c0p + 2*k2);
                    float2 c1 = *(const float2*)(c1p + 2*k2);
                    float2 c2 = *(const float2*)(c2p + 2*k2);
                    float2 c3 = *(const float2*)(c3p + 2*k2);
                    float4 wA = *(const float4*)(Wg + (2*k2)*64 + d0);
                    float4 wB = *(const float4*)(Wg + (2*k2 + 1)*64 + d0);
                    acc[0][0] = fmaf(c0.x, wA.x, acc[0][0]); acc[0][0] = fmaf(c0.y, wB.x, acc[0][0]);
                    acc[0][1] = fmaf(c0.x, wA.y, acc[0][1]); acc[0][1] = fmaf(c0.y, wB.y, acc[0][1]);
                    acc[0][2] = fmaf(c0.x, wA.z, acc[0][2]); acc[0][2] = fmaf(c0.y, wB.z, acc[0][2]);
                    acc[0][3] = fmaf(c0.x, wA.w, acc[0][3]); acc[0][3] = fmaf(c0.y, wB.w, acc[0][3]);
                    acc[1][0] = fmaf(c1.x, wA.x, acc[1][0]); acc[1][0] = fmaf(c1.y, wB.x, acc[1][0]);
                    acc[1][1] = fmaf(c1.x, wA.y, acc[1][1]); acc[1][1] = fmaf(c1.y, wB.y, acc[1][1]);
                    acc[1][2] = fmaf(c1.x, wA.z, acc[1][2]); acc[1][2] = fmaf(c1.y, wB.z, acc[1][2]);
                    acc[1][3] = fmaf(c1.x, wA.w, acc[1][3]); acc[1][3] = fmaf(c1.y, wB.w, acc[1][3]);
                    acc[2][0] = fmaf(c2.x, wA.x, acc[2][0]); acc[2][0] = fmaf(c2.y, wB.x, acc[2][0]);
                    acc[2][1] = fmaf(c2.x, wA.y, acc[2][1]); acc[2][1] = fmaf(c2.y, wB.y, acc[2][1]);
                    acc[2][2] = fmaf(c2.x, wA.z, acc[2][2]); acc[2][2] = fmaf(c2.y, wB.z, acc[2][2]);
                    acc[2][3] = fmaf(c2.x, wA.w, acc[2][3]); acc[2][3] = fmaf(c2.y, wB.w, acc[2][3]);
                    acc[3][0] = fmaf(c3.x, wA.x, acc[3][0]); acc[3][0] = fmaf(c3.y, wB.x, acc[3][0]);
                    acc[3][1] = fmaf(c3.x, wA.y, acc[3][1]); acc[3][1] = fmaf(c3.y, wB.y, acc[3][1]);
                    acc[3][2] = fmaf(c3.x, wA.z, acc[3][2]); acc[3][2] = fmaf(c3.y, wB.z, acc[3][2]);
                    acc[3][3] = fmaf(c3.x, wA.w, acc[3][3]); acc[3][3] = fmaf(c3.y, wB.w, acc[3][3]);
                }
                #pragma unroll
                for (int i = 0; i < 4; i++)
                    #pragma unroll
                    for (int j = 0; j < 4; j++)
                        acc[i][j] += __shfl_xor_sync(0xffffffffu, acc[i][j], 1);

                if (ks == 0) {
                    #pragma unroll
                    for (int i = 0; i < 4; i++) {
                        int bb2 = bb[i];
                        float4 cx = *(const float4*)(cxsB + bb2*64 + d0);
                        float4 h1 = *(const float4*)(zcs + bb2*KR + 68 + d0);
                        float4 u  = *(const float4*)(usB + bb2*64 + d0);
                        float4 v;
                        v.x = h1.x + u.x*(tanhfast(acc[i][0] + cx.x) - h1.x);
                        v.y = h1.y + u.y*(tanhfast(acc[i][1] + cx.y) - h1.y);
                        v.z = h1.z + u.z*(tanhfast(acc[i][2] + cx.z) - h1.z);
                        v.w = h1.w + u.w*(tanhfast(acc[i][3] + cx.w) - h1.w);
                        *(float4*)(hnext + (size_t)(bb2*N_ + n)*D_ + d0) = v;
                        *(float4*)(hsB + bb2*64 + d0) = v;
                        if (t == lenS[bb2] - 1)
                            *(float4*)(out + (size_t)(bb2*N_ + n)*D_ + d0) = v;
                    }
                }
            } else if (warp >= BG4) {
                int w2 = warp - BG4;
                int nU = B_ - nB;
                int pairs = (nU + 1) >> 1;
                if (w2 < pairs) {
                    int iu = w2 * 2;
                    int dd = lane * 2;
                    #pragma unroll
                    for (int rep = 0; rep < 2; rep++) {
                        if (iu + rep < nU) {
                            int bb2 = listU[iu + rep];
                            float2 v = *(const float2*)(hsB + bb2*64 + dd);
                            *(float2*)(hnext + (size_t)(bb2*N_ + n)*D_ + dd) = v;
                            if (t == lenS[bb2] - 1)
                                *(float2*)(out + (size_t)(bb2*N_ + n)*D_ + dd) = v;
                        }
                    }
                }
            }
        }
        __syncthreads();
    }
}

extern "C" void kernel_launch(void* const* d_in, const int* in_sizes, int n_in,
                              void* d_out, int out_size) {
    const float* obs     = (const float*)d_in[0];
    const float* mask    = (const float*)d_in[2];
    const int*   lengths = (const int*)d_in[5];
    const float* avg     = (const float*)d_in[6];
    const float* vpe     = (const float*)d_in[7];
    const float* rarW    = (const float*)d_in[8];
    const float* adjI    = (const float*)d_in[9];
    const float* W1      = (const float*)d_in[10];
    const float* b1      = (const float*)d_in[11];
    const float* W2      = (const float*)d_in[12];
    const float* b2      = (const float*)d_in[13];
    const float* Wu      = (const float*)d_in[14];
    const float* bu      = (const float*)d_in[15];
    const float* Wr      = (const float*)d_in[16];
    const float* br      = (const float*)d_in[17];
    const float* Wc      = (const float*)d_in[18];
    const float* bc      = (const float*)d_in[19];
    float* out = (float*)d_out;

    cudaFuncSetAttribute(cgrnn_persistent,
                         cudaFuncAttributeMaxDynamicSharedMemorySize, SMEM_BYTES);
    cgrnn_persistent<<<GRID, BLOCK, SMEM_BYTES>>>(
        obs, mask, lengths, avg, vpe, rarW, adjI,
        W1, b1, W2, b2, Wr, br, Wu, bu, Wc, bc, out);
}